// round 12
// baseline (speedup 1.0000x reference)
#include <cuda_runtime.h>
#include <cuda_bf16.h>
#include <math.h>

#define BB   8
#define CH   32
#define NN   500
#define TT0  256
#define SCC  256

#define MAXELEM (BB*CH*TT0*NN)   // 32,768,000 floats
#define SROWS   32768            // max GEMM rows (layer 0: 8*32*128)
#define SW      512              // padded K width for bf16 splits

__device__ float g_h0[MAXELEM];
__device__ float g_h1[MAXELEM];
__device__ float g_hg[MAXELEM/2];
__device__ float g_p1a[MAXELEM/2];
__device__ float g_p2a[MAXELEM/2];
__device__ float g_p1b[MAXELEM/2];
__device__ float g_p2b[MAXELEM/2];
__device__ float g_skip[BB*SCC*NN];
__device__ float g_e1[BB*512*NN];

// bf16 split buffers; row width SW=512. Pad cols 500..511 are NEVER written and
// __device__ globals are zero-initialized, so they stay zero across graph replays.
__device__ __nv_bfloat16 g_hg_hi [SROWS*SW];
__device__ __nv_bfloat16 g_hg_lo [SROWS*SW];
__device__ __nv_bfloat16 g_p1a_hi[SROWS*SW];
__device__ __nv_bfloat16 g_p1a_lo[SROWS*SW];
__device__ __nv_bfloat16 g_p1b_hi[SROWS*SW];
__device__ __nv_bfloat16 g_p1b_lo[SROWS*SW];
// transposed+split adjacencies: Bt[n][k] = Adj[k][n], 512x512 (pads stay zero)
__device__ __nv_bfloat16 g_bt0_hi[SW*SW];
__device__ __nv_bfloat16 g_bt0_lo[SW*SW];
__device__ __nv_bfloat16 g_bt1_hi[SW*SW];
__device__ __nv_bfloat16 g_bt1_lo[SW*SW];

typedef unsigned long long u64;
typedef unsigned int u32;

__device__ __forceinline__ u64 pack_dup(float a){
    u64 r; unsigned ai = __float_as_uint(a);
    asm("mov.b64 %0, {%1, %1};" : "=l"(r) : "r"(ai));
    return r;
}
__device__ __forceinline__ void fma2(u64 &acc, u64 a, u64 b){
    asm("fma.rn.f32x2 %0, %1, %2, %0;" : "+l"(acc) : "l"(a), "l"(b));
}
__device__ __forceinline__ float2 unpack2(u64 v){
    unsigned lo, hi;
    asm("mov.b64 {%0, %1}, %2;" : "=r"(lo), "=r"(hi) : "l"(v));
    return make_float2(__uint_as_float(lo), __uint_as_float(hi));
}

// ---------------- PTX helpers: cp.async + ldmatrix + mma (all plain sm_80+) ----
__device__ __forceinline__ u32 smem_u32(const void* p){
    u32 a; asm("{ .reg .u64 t; cvta.to.shared.u64 t, %1; cvt.u32.u64 %0, t; }" : "=r"(a) : "l"(p));
    return a;
}
__device__ __forceinline__ void cp16(u32 s, const void* g){
    asm volatile("cp.async.cg.shared.global [%0], [%1], 16;" :: "r"(s), "l"(g));
}
__device__ __forceinline__ void cp_commit(){ asm volatile("cp.async.commit_group;" ::: "memory"); }
template<int N> __device__ __forceinline__ void cp_wait(){ asm volatile("cp.async.wait_group %0;" :: "n"(N) : "memory"); }

__device__ __forceinline__ void ldsm4(u32* r, u32 addr){
    asm volatile("ldmatrix.sync.aligned.m8n8.x4.shared.b16 {%0,%1,%2,%3}, [%4];"
        : "=r"(r[0]), "=r"(r[1]), "=r"(r[2]), "=r"(r[3]) : "r"(addr));
}
__device__ __forceinline__ void mma16816(float* d, const u32* a, u32 b0, u32 b1){
    asm volatile(
        "mma.sync.aligned.m16n8k16.row.col.f32.bf16.bf16.f32 "
        "{%0,%1,%2,%3}, {%4,%5,%6,%7}, {%8,%9}, {%0,%1,%2,%3};"
        : "+f"(d[0]), "+f"(d[1]), "+f"(d[2]), "+f"(d[3])
        : "r"(a[0]), "r"(a[1]), "r"(a[2]), "r"(a[3]), "r"(b0), "r"(b1));
}

// ---------------------------------------------------------------------------
// prep: block r (0..499) does BOTH
//   (a) bt0[.][r] = split(A0[r][.])           (transpose of A0)
//   (b) adp row r = softmax(relu(nv1@nv2))[r]; bt1[.][r] = split(adp[r][.])
// ---------------------------------------------------------------------------
__global__ void __launch_bounds__(512) prep_kernel(
    const float* __restrict__ A0,
    const float* __restrict__ nv1, const float* __restrict__ nv2,
    __nv_bfloat16* __restrict__ b0h, __nv_bfloat16* __restrict__ b0l,
    __nv_bfloat16* __restrict__ b1h, __nv_bfloat16* __restrict__ b1l)
{
    __shared__ float sv[NN];
    __shared__ float sred[16];
    __shared__ float sres;
    int r = blockIdx.x, tid = threadIdx.x;

    for (int j = tid; j < NN; j += 512){
        float v = A0[(size_t)r*NN + j];
        __nv_bfloat16 h = __float2bfloat16(v);
        __nv_bfloat16 l = __float2bfloat16(v - __bfloat162float(h));
        b0h[(size_t)j*SW + r] = h;
        b0l[(size_t)j*SW + r] = l;
    }

    float e1[10];
    #pragma unroll
    for (int k = 0; k < 10; k++) e1[k] = nv1[r*10 + k];

    float lmax = -1e30f;
    for (int j = tid; j < NN; j += 512){
        float v = 0.f;
        #pragma unroll
        for (int k = 0; k < 10; k++) v += e1[k] * nv2[k*NN + j];
        v = fmaxf(v, 0.f);
        sv[j] = v;
        lmax = fmaxf(lmax, v);
    }
    #pragma unroll
    for (int off = 16; off; off >>= 1) lmax = fmaxf(lmax, __shfl_xor_sync(0xffffffffu, lmax, off));
    if ((tid & 31) == 0) sred[tid >> 5] = lmax;
    __syncthreads();
    if (tid < 16){
        float v = sred[tid];
        #pragma unroll
        for (int off = 8; off; off >>= 1) v = fmaxf(v, __shfl_xor_sync(0xffffu, v, off));
        if (tid == 0) sres = v;
    }
    __syncthreads();
    float bmax = sres;
    float lsum = 0.f;
    for (int j = tid; j < NN; j += 512){
        float e = expf(sv[j] - bmax);
        sv[j] = e;
        lsum += e;
    }
    #pragma unroll
    for (int off = 16; off; off >>= 1) lsum += __shfl_xor_sync(0xffffffffu, lsum, off);
    __syncthreads();
    if ((tid & 31) == 0) sred[tid >> 5] = lsum;
    __syncthreads();
    if (tid < 16){
        float v = sred[tid];
        #pragma unroll
        for (int off = 8; off; off >>= 1) v += __shfl_xor_sync(0xffffu, v, off);
        if (tid == 0) sres = v;
    }
    __syncthreads();
    float inv = 1.0f / sres;
    for (int j = tid; j < NN; j += 512){
        float v = sv[j] * inv;
        __nv_bfloat16 h = __float2bfloat16(v);
        __nv_bfloat16 l = __float2bfloat16(v - __bfloat162float(h));
        b1h[(size_t)j*SW + r] = h;
        b1l[(size_t)j*SW + r] = l;
    }
}

// ---------------------------------------------------------------------------
// start conv (coalesced transpose): x [B,2,N,T] -> c0 [B,32,256,N], slot=255-t
// 32x32 (t,n) tiles staged through smem; reads coalesced over t, writes over n.
// ---------------------------------------------------------------------------
__global__ void __launch_bounds__(256) start_conv_kernel(
    const float* __restrict__ x, const float* __restrict__ w,
    const float* __restrict__ bias, float* __restrict__ h)
{
    __shared__ float xs0[32][33], xs1[32][33];
    __shared__ float wv[64], bv[32];
    int t0 = blockIdx.x*32, n0 = blockIdx.y*32, b = blockIdx.z;
    int tx = threadIdx.x & 31, ty = threadIdx.x >> 5;   // ty 0..7
    if (threadIdx.x < 64) wv[threadIdx.x] = w[threadIdx.x];
    if (threadIdx.x < 32) bv[threadIdx.x] = bias[threadIdx.x];

    #pragma unroll
    for (int r = 0; r < 4; r++){
        int nl = ty + r*8;
        int n = n0 + nl;
        float v0 = 0.f, v1 = 0.f;
        if (n < NN){
            v0 = x[((size_t)(b*2 + 0)*NN + n)*TT0 + t0 + tx];
            v1 = x[((size_t)(b*2 + 1)*NN + n)*TT0 + t0 + tx];
        }
        xs0[tx][nl] = v0;   // [t_local][n_local]
        xs1[tx][nl] = v1;
    }
    __syncthreads();

    int n = n0 + tx;
    bool ok = (n < NN);
    #pragma unroll
    for (int p = 0; p < 4; p++){
        int tl = ty + p*8;
        int slot = TT0 - 1 - (t0 + tl);
        float x0 = xs0[tl][tx], x1 = xs1[tl][tx];
        if (ok){
            #pragma unroll
            for (int o = 0; o < 32; o++){
                h[((size_t)(b*32 + o)*TT0 + slot)*NN + n] = wv[o*2]*x0 + wv[o*2+1]*x1 + bv[o];
            }
        }
    }
}

// ---------------------------------------------------------------------------
// gated dilated conv on COMPACT slots; also emits bf16 split of hg
// ---------------------------------------------------------------------------
__global__ void __launch_bounds__(128) gated_conv_kernel(
    const float* __restrict__ c, float* __restrict__ hg,
    __nv_bfloat16* __restrict__ hgh, __nv_bfloat16* __restrict__ hgl,
    const float* __restrict__ fw, const float* __restrict__ fb,
    const float* __restrict__ gw, const float* __restrict__ gb,
    int Cin, int Cout)
{
    __shared__ __align__(16) u64 wpk[32][32][4];
    int tid = threadIdx.x;
    for (int idx = tid; idx < 32*32; idx += 128){
        int cc = idx >> 5, o = idx & 31;
        wpk[cc][o][0] = pack_dup(fw[(o*32 + cc)*2 + 0]);
        wpk[cc][o][1] = pack_dup(fw[(o*32 + cc)*2 + 1]);
        wpk[cc][o][2] = pack_dup(gw[(o*32 + cc)*2 + 0]);
        wpk[cc][o][3] = pack_dup(gw[(o*32 + cc)*2 + 1]);
    }
    __syncthreads();
    int b = blockIdx.z, m = blockIdx.y;
    int n = (blockIdx.x*128 + tid)*2;
    if (n >= NN) return;

    const float* base0 = c + ((size_t)(b*32)*Cin + 2*m + 1)*NN + n;
    const float* base1 = c + ((size_t)(b*32)*Cin + 2*m)*NN + n;
    size_t cs = (size_t)Cin*NN;

    #pragma unroll 1
    for (int half = 0; half < 2; half++){
        u64 accf[16], accg[16];
        #pragma unroll
        for (int oo = 0; oo < 16; oo++){ accf[oo] = 0ull; accg[oo] = 0ull; }
        for (int cc = 0; cc < 32; cc++){
            u64 in0 = *(const u64*)(base0 + cc*cs);
            u64 in1 = *(const u64*)(base1 + cc*cs);
            const u64* wp = &wpk[cc][half*16][0];
            #pragma unroll
            for (int oo = 0; oo < 16; oo++){
                ulonglong2 wA = *(const ulonglong2*)(wp + oo*4);
                ulonglong2 wB = *(const ulonglong2*)(wp + oo*4 + 2);
                fma2(accf[oo], wA.x, in0);
                fma2(accf[oo], wA.y, in1);
                fma2(accg[oo], wB.x, in0);
                fma2(accg[oo], wB.y, in1);
            }
        }
        #pragma unroll
        for (int oo = 0; oo < 16; oo++){
            int o = half*16 + oo;
            float2 f = unpack2(accf[oo]);
            float2 g = unpack2(accg[oo]);
            float fbv = fb[o], gbv = gb[o];
            float2 out;
            out.x = tanhf(f.x + fbv) * (1.0f/(1.0f + expf(-(g.x + gbv))));
            out.y = tanhf(f.y + fbv) * (1.0f/(1.0f + expf(-(g.y + gbv))));
            size_t row = (size_t)(b*32 + o)*Cout + m;
            *(float2*)(hg + row*NN + n) = out;
            __nv_bfloat162 hv, lv;
            hv.x = __float2bfloat16(out.x);
            lv.x = __float2bfloat16(out.x - __bfloat162float(hv.x));
            hv.y = __float2bfloat16(out.y);
            lv.y = __float2bfloat16(out.y - __bfloat162float(hv.y));
            *(__nv_bfloat162*)(hgh + row*SW + n) = hv;
            *(__nv_bfloat162*)(hgl + row*SW + n) = lv;
        }
    }
}

// ---------------------------------------------------------------------------
// skip: slot 0 of hg is the last time index; 8 output channels per block
// ---------------------------------------------------------------------------
__global__ void __launch_bounds__(128) skip_kernel(
    const float* __restrict__ hg, const float* __restrict__ sw,
    const float* __restrict__ sb, float* __restrict__ skip,
    int Cout, int first)
{
    __shared__ __align__(16) float ws[32*8];    // ws[c*8+j] = sw[(o0+j)*32+c]
    int o0 = blockIdx.y*8, b = blockIdx.z, tid = threadIdx.x;
    for (int i = tid; i < 32*8; i += 128){
        int c = i >> 3, j = i & 7;
        ws[i] = sw[(o0 + j)*32 + c];
    }
    __syncthreads();
    int n = blockIdx.x*128 + tid;
    if (n >= NN) return;
    const float* p = hg + ((size_t)(b*32)*Cout)*NN + n;
    size_t cs = (size_t)Cout*NN;
    float acc[8];
    #pragma unroll
    for (int j = 0; j < 8; j++) acc[j] = sb[o0 + j];
    #pragma unroll
    for (int c = 0; c < 32; c++){
        float v = p[c*cs];
        float4 w0 = *(const float4*)&ws[c*8];
        float4 w1 = *(const float4*)&ws[c*8 + 4];
        acc[0] += w0.x*v; acc[1] += w0.y*v; acc[2] += w0.z*v; acc[3] += w0.w*v;
        acc[4] += w1.x*v; acc[5] += w1.y*v; acc[6] += w1.z*v; acc[7] += w1.w*v;
    }
    #pragma unroll
    for (int j = 0; j < 8; j++){
        float* dst = skip + ((size_t)b*SCC + o0 + j)*NN + n;
        if (first) *dst = acc[j];
        else       *dst += acc[j];
    }
}

// ---------------------------------------------------------------------------
// DUAL bf16 HMMA GEMM, 8 warps, 64x128 CTA tile, 3 CTAs/SM, ONE sync/chunk.
// FILL for chunk kc+2 issues between ks=0 fragment loads and MMAs so cp.async
// issue overlaps tensor work.
// ---------------------------------------------------------------------------
__global__ void __launch_bounds__(256, 3) mma_gemm_dual(
    const __nv_bfloat16* __restrict__ Ah0, const __nv_bfloat16* __restrict__ Al0,
    const __nv_bfloat16* __restrict__ Ah1, const __nv_bfloat16* __restrict__ Al1,
    const __nv_bfloat16* __restrict__ Bh0, const __nv_bfloat16* __restrict__ Bl0,
    const __nv_bfloat16* __restrict__ Bh1, const __nv_bfloat16* __restrict__ Bl1,
    float* __restrict__ C0, float* __restrict__ C1,
    __nv_bfloat16* __restrict__ Ch0, __nv_bfloat16* __restrict__ Cl0,
    __nv_bfloat16* __restrict__ Ch1, __nv_bfloat16* __restrict__ Cl1,
    int write_split)
{
    extern __shared__ __align__(128) char smem[];   // 3 x 24576 bytes
    const u32 sb = smem_u32(smem);
    const int tid = threadIdx.x;
    const int wid = tid >> 5, lane = tid & 31;
    const int wm = wid >> 2, wn = wid & 3;          // 2x4 warp grid, 32x32 tiles
    const int m0 = blockIdx.x << 6, n0 = blockIdx.y << 7;
    const int z = blockIdx.z;

    const __nv_bfloat16* Ahi = z ? Ah1 : Ah0;
    const __nv_bfloat16* Alo = z ? Al1 : Al0;
    const __nv_bfloat16* Bhi = z ? Bh1 : Bh0;
    const __nv_bfloat16* Blo = z ? Bl1 : Bl0;
    float* C = z ? C1 : C0;
    __nv_bfloat16* Chi = z ? Ch1 : Ch0;
    __nv_bfloat16* Clo = z ? Cl1 : Cl0;

    float acc[2][4][4];
    #pragma unroll
    for (int mt = 0; mt < 2; mt++)
        #pragma unroll
        for (int nt = 0; nt < 4; nt++)
            #pragma unroll
            for (int r = 0; r < 4; r++) acc[mt][nt][r] = 0.f;

    const __nv_bfloat16* baseAh = Ahi + (size_t)m0*SW;
    const __nv_bfloat16* baseAl = Alo + (size_t)m0*SW;
    const __nv_bfloat16* baseBh = Bhi + (size_t)n0*SW;
    const __nv_bfloat16* baseBl = Blo + (size_t)n0*SW;

    const int fr = tid >> 2, fc = tid & 3;
    const int fr2 = fr + 64;
    const u32 fdA  = (u32)(fr*64  + (fc ^ ((fr  >> 1) & 3))*16);
    const u32 fdB2 = (u32)(fr2*64 + (fc ^ ((fr2 >> 1) & 3))*16);
    const size_t fsA  = (size_t)fr*SW  + fc*8;
    const size_t fsB2 = (size_t)fr2*SW + fc*8;

    #define FILL(kc, bufaddr) do {                                   \
        size_t ko = (size_t)(kc)*32;                                 \
        cp16((bufaddr) +     0 + fdA,  baseAh + fsA  + ko);          \
        cp16((bufaddr) +  4096 + fdA,  baseAl + fsA  + ko);          \
        cp16((bufaddr) +  8192 + fdA,  baseBh + fsA  + ko);          \
        cp16((bufaddr) +  8192 + fdB2, baseBh + fsB2 + ko);          \
        cp16((bufaddr) + 16384 + fdA,  baseBl + fsA  + ko);          \
        cp16((bufaddr) + 16384 + fdB2, baseBl + fsB2 + ko);          \
        cp_commit();                                                 \
    } while(0)

    FILL(0, sb);
    FILL(1, sb + 24576);

    int st = 0;  // stage index of current chunk
    #pragma unroll 1
    for (int kc = 0; kc < 16; kc++){
        u32 cur = sb + (u32)st*24576;
        if (kc + 1 < 16) cp_wait<1>();
        else             cp_wait<0>();
        __syncthreads();                 // all warps done with stage (st-1)%3

        #pragma unroll
        for (int ks = 0; ks < 2; ks++){
            u32 ah[2][4], al[2][4], bh[2][4], bl[2][4];
            #pragma unroll
            for (int mt = 0; mt < 2; mt++){
                int row = wm*32 + mt*16 + (lane & 15);
                int c = ks*2 + (lane >> 4);
                int csw = c ^ ((row >> 1) & 3);
                u32 a = cur + (u32)(row*64 + csw*16);
                ldsm4(ah[mt], a);
                ldsm4(al[mt], a + 4096);
            }
            #pragma unroll
            for (int np = 0; np < 2; np++){
                int row = wn*32 + np*16 + (lane & 7) + ((lane >> 4) << 3);
                int c = ks*2 + ((lane >> 3) & 1);
                int csw = c ^ ((row >> 1) & 3);
                u32 a = cur + (u32)(8192 + row*64 + csw*16);
                ldsm4(bh[np], a);
                ldsm4(bl[np], a + 8192);
            }
            if (ks == 0 && kc + 2 < 16){
                int ns = st + 2; if (ns >= 3) ns -= 3;
                FILL(kc + 2, sb + (u32)ns*24576);
            }
            #pragma unroll
            for (int mt = 0; mt < 2; mt++)
                #pragma unroll
                for (int nt = 0; nt < 4; nt++){
                    u32 b0h = bh[nt >> 1][(nt & 1)*2], b1h = bh[nt >> 1][(nt & 1)*2 + 1];
                    u32 b0l = bl[nt >> 1][(nt & 1)*2], b1l = bl[nt >> 1][(nt & 1)*2 + 1];
                    mma16816(acc[mt][nt], ah[mt], b0h, b1h);
                    mma16816(acc[mt][nt], ah[mt], b0l, b1l);
                    mma16816(acc[mt][nt], al[mt], b0h, b1h);
                }
        }
        st++; if (st >= 3) st -= 3;
    }
    #undef FILL

    // epilogue: c0=C[g][2t], c1=C[g][2t+1], c2=C[g+8][2t], c3=C[g+8][2t+1]
    int g = lane >> 2, t = lane & 3;
    #pragma unroll
    for (int mt = 0; mt < 2; mt++){
        #pragma unroll
        for (int nt = 0; nt < 4; nt++){
            int col = n0 + wn*32 + nt*8 + 2*t;
            if (col >= NN) continue;
            int row = m0 + wm*32 + mt*16 + g;
            float* d = acc[mt][nt];
            *(float2*)(C + (size_t)row*NN + col)       = make_float2(d[0], d[1]);
            *(float2*)(C + (size_t)(row + 8)*NN + col) = make_float2(d[2], d[3]);
            if (write_split){
                __nv_bfloat162 hv, lv;
                hv.x = __float2bfloat16(d[0]);
                lv.x = __float2bfloat16(d[0] - __bfloat162float(hv.x));
                hv.y = __float2bfloat16(d[1]);
                lv.y = __float2bfloat16(d[1] - __bfloat162float(hv.y));
                *(__nv_bfloat162*)(Chi + (size_t)row*SW + col) = hv;
                *(__nv_bfloat162*)(Clo + (size_t)row*SW + col) = lv;
                hv.x = __float2bfloat16(d[2]);
                lv.x = __float2bfloat16(d[2] - __bfloat162float(hv.x));
                hv.y = __float2bfloat16(d[3]);
                lv.y = __float2bfloat16(d[3] - __bfloat162float(hv.y));
                *(__nv_bfloat162*)(Chi + (size_t)(row + 8)*SW + col) = hv;
                *(__nv_bfloat162*)(Clo + (size_t)(row + 8)*SW + col) = lv;
            }
        }
    }
}

// ---------------------------------------------------------------------------
// combine on COMPACT slots
// ---------------------------------------------------------------------------
__global__ void __launch_bounds__(128) combine_kernel(
    const float* __restrict__ hg,  const float* __restrict__ p1a,
    const float* __restrict__ p2a, const float* __restrict__ p1b,
    const float* __restrict__ p2b, const float* __restrict__ res,
    float* __restrict__ hout,
    const float* __restrict__ gw,  const float* __restrict__ gb,
    const float* __restrict__ bng, const float* __restrict__ bnb,
    int Cout, int Cin)
{
    __shared__ __align__(16) u64 wpk[160][32];
    int tid = threadIdx.x;
    for (int idx = tid; idx < 160*32; idx += 128){
        int c = idx >> 5, o = idx & 31;
        wpk[c][o] = pack_dup(gw[o*160 + c]);
    }
    __syncthreads();
    int b = blockIdx.z, m = blockIdx.y;
    int n = (blockIdx.x*128 + tid)*2;
    if (n >= NN) return;

    u64 acc[32];
    #pragma unroll
    for (int o = 0; o < 32; o++) acc[o] = 0ull;

    size_t pt = ((size_t)(b*32)*Cout + m)*NN + n;
    size_t cs = (size_t)Cout*NN;
    #pragma unroll 1
    for (int s5 = 0; s5 < 5; s5++){
        const float* p = (s5 == 0 ? hg : s5 == 1 ? p1a : s5 == 2 ? p2a : s5 == 3 ? p1b : p2b) + pt;
        for (int cc = 0; cc < 32; cc++){
            u64 in = *(const u64*)(p + cc*cs);
            const u64* w = &wpk[s5*32 + cc][0];
            #pragma unroll
            for (int j = 0; j < 16; j++){
                ulonglong2 wv = *(const ulonglong2*)(w + 2*j);
                fma2(acc[2*j],   wv.x, in);
                fma2(acc[2*j+1], wv.y, in);
            }
        }
    }
    const float invs = 1.0f / sqrtf(1.0f + 1e-5f);
    #pragma unroll
    for (int o = 0; o < 32; o++){
        float2 a = unpack2(acc[o]);
        float2 r = *(const float2*)(res + ((size_t)(b*32 + o)*Cin + 2*m)*NN + n);
        float sc = bng[o]*invs, bbv = bnb[o], gbv = gb[o];
        float2 out;
        out.x = (a.x + gbv + r.x)*sc + bbv;
        out.y = (a.y + gbv + r.y)*sc + bbv;
        *(float2*)(hout + ((size_t)(b*32 + o)*Cout + m)*NN + n) = out;
    }
}

// ---------------------------------------------------------------------------
// end convs (T=1): end1 register-tiled, 8 output channels per block
// ---------------------------------------------------------------------------
__global__ void __launch_bounds__(128) end1_kernel(
    const float* __restrict__ sk, const float* __restrict__ w,
    const float* __restrict__ b1, float* __restrict__ e1)
{
    __shared__ __align__(16) float ws[256*8];   // ws[c*8+j] = w[(o0+j)*256+c]
    int o0 = blockIdx.y*8, b = blockIdx.z, tid = threadIdx.x;
    for (int i = tid; i < 256*8; i += 128){
        int c = i >> 3, j = i & 7;
        ws[i] = w[(o0 + j)*256 + c];
    }
    __syncthreads();
    int n = blockIdx.x*128 + tid;
    if (n >= NN) return;
    float acc[8];
    #pragma unroll
    for (int j = 0; j < 8; j++) acc[j] = b1[o0 + j];
    const float* sp = sk + (size_t)b*SCC*NN + n;
    #pragma unroll 4
    for (int c = 0; c < 256; c++){
        float v = fmaxf(sp[(size_t)c*NN], 0.f);
        float4 w0 = *(const float4*)&ws[c*8];
        float4 w1 = *(const float4*)&ws[c*8 + 4];
        acc[0] += w0.x*v; acc[1] += w0.y*v; acc[2] += w0.z*v; acc[3] += w0.w*v;
        acc[4] += w1.x*v; acc[5] += w1.y*v; acc[6] += w1.z*v; acc[7] += w1.w*v;
    }
    #pragma unroll
    for (int j = 0; j < 8; j++)
        e1[((size_t)b*512 + o0 + j)*NN + n] = fmaxf(acc[j], 0.f);
}

__global__ void __launch_bounds__(128) end2_kernel(
    const float* __restrict__ e1g, const float* __restrict__ w,
    const float* __restrict__ b2, float* __restrict__ out)
{
    __shared__ float ws[512];
    int o = blockIdx.y, b = blockIdx.z, tid = threadIdx.x;
    for (int i = tid; i < 512; i += 128) ws[i] = w[o*512 + i];
    __syncthreads();
    int n = blockIdx.x*128 + tid;
    if (n >= NN) return;
    float acc = b2[o];
    const float* p = e1g + (size_t)b*512*NN + n;
    #pragma unroll 8
    for (int c = 0; c < 512; c++) acc += ws[c] * p[(size_t)c*NN];
    out[((size_t)b*12 + o)*NN + n] = acc;
}

// ---------------------------------------------------------------------------
extern "C" void kernel_launch(void* const* d_in, const int* in_sizes, int n_in,
                              void* d_out, int out_size)
{
    const float* x       = (const float*)d_in[0];
    const float* A0      = (const float*)d_in[1];
    const float* start_w = (const float*)d_in[2];
    const float* start_b = (const float*)d_in[3];
    const float* filt_w  = (const float*)d_in[4];
    const float* filt_b  = (const float*)d_in[5];
    const float* gate_w  = (const float*)d_in[6];
    const float* gate_b  = (const float*)d_in[7];
    const float* skip_w  = (const float*)d_in[8];
    const float* skip_b  = (const float*)d_in[9];
    const float* gcn_w   = (const float*)d_in[10];
    const float* gcn_b   = (const float*)d_in[11];
    const float* bn_g    = (const float*)d_in[12];
    const float* bn_b    = (const float*)d_in[13];
    const float* nv1     = (const float*)d_in[14];
    const float* nv2     = (const float*)d_in[15];
    const float* e1w     = (const float*)d_in[16];
    const float* e1b     = (const float*)d_in[17];
    const float* e2w     = (const float*)d_in[18];
    const float* e2b     = (const float*)d_in[19];
    float* out = (float*)d_out;

    float *h0, *h1, *hg, *p1a, *p2a, *p1b, *p2b, *skip, *e1;
    __nv_bfloat16 *hgh, *hgl, *p1ah, *p1al, *p1bh, *p1bl;
    __nv_bfloat16 *bt0h, *bt0l, *bt1h, *bt1l;
    cudaGetSymbolAddress((void**)&h0,  g_h0);
    cudaGetSymbolAddress((void**)&h1,  g_h1);
    cudaGetSymbolAddress((void**)&hg,  g_hg);
    cudaGetSymbolAddress((void**)&p1a, g_p1a);
    cudaGetSymbolAddress((void**)&p2a, g_p2a);
    cudaGetSymbolAddress((void**)&p1b, g_p1b);
    cudaGetSymbolAddress((void**)&p2b, g_p2b);
    cudaGetSymbolAddress((void**)&skip, g_skip);
    cudaGetSymbolAddress((void**)&e1,  g_e1);
    cudaGetSymbolAddress((void**)&hgh,  g_hg_hi);
    cudaGetSymbolAddress((void**)&hgl,  g_hg_lo);
    cudaGetSymbolAddress((void**)&p1ah, g_p1a_hi);
    cudaGetSymbolAddress((void**)&p1al, g_p1a_lo);
    cudaGetSymbolAddress((void**)&p1bh, g_p1b_hi);
    cudaGetSymbolAddress((void**)&p1bl, g_p1b_lo);
    cudaGetSymbolAddress((void**)&bt0h, g_bt0_hi);
    cudaGetSymbolAddress((void**)&bt0l, g_bt0_lo);
    cudaGetSymbolAddress((void**)&bt1h, g_bt1_hi);
    cudaGetSymbolAddress((void**)&bt1l, g_bt1_lo);

    const int MMA_SMEM = 3*24576;
    cudaFuncSetAttribute(mma_gemm_dual, cudaFuncAttributeMaxDynamicSharedMemorySize, MMA_SMEM);

    // side stream + events, created once (host-side objects only)
    static cudaStream_t s2 = nullptr;
    static cudaEvent_t evFork = nullptr, evPrep = nullptr, evG = nullptr, evSkip = nullptr;
    if (s2 == nullptr){
        cudaStreamCreateWithFlags(&s2, cudaStreamNonBlocking);
        cudaEventCreateWithFlags(&evFork, cudaEventDisableTiming);
        cudaEventCreateWithFlags(&evPrep, cudaEventDisableTiming);
        cudaEventCreateWithFlags(&evG,    cudaEventDisableTiming);
        cudaEventCreateWithFlags(&evSkip, cudaEventDisableTiming);
    }

    // fork s2 off the main stream, run prep there
    cudaEventRecord(evFork, 0);
    cudaStreamWaitEvent(s2, evFork, 0);
    prep_kernel<<<NN, 512, 0, s2>>>(A0, nv1, nv2, bt0h, bt0l, bt1h, bt1l);
    cudaEventRecord(evPrep, s2);

    start_conv_kernel<<<dim3(TT0/32, (NN + 31)/32, BB), 256>>>(x, start_w, start_b, h0);

    int Cin = TT0;
    float* hcur = h0;
    float* hnext = h1;
    for (int i = 0; i < 8; i++){
        int Cout = Cin >> 1;

        if (i > 0) cudaStreamWaitEvent(0, evSkip, 0);   // skip(i-1) done before hg overwrite

        gated_conv_kernel<<<dim3(2, Cout, BB), 128>>>(
            hcur, hg, hgh, hgl,
            filt_w + (size_t)i*32*32*2, filt_b + (size_t)i*32,
            gate_w + (size_t)i*32*32*2, gate_b + (size_t)i*32,
            Cin, Cout);

        cudaEventRecord(evG, 0);
        cudaStreamWaitEvent(s2, evG, 0);
        skip_kernel<<<dim3(4, SCC/8, BB), 128, 0, s2>>>(
            hg, skip_w + (size_t)i*SCC*32, skip_b + (size_t)i*SCC,
            skip, Cout, (i == 0) ? 1 : 0);
        cudaEventRecord(evSkip, s2);

        if (i < 7){
            if (i == 0) cudaStreamWaitEvent(0, evPrep, 0);
            int M = BB*CH*Cout;
            dim3 gg(M >> 6, 4, 2);
            mma_gemm_dual<<<gg, 256, MMA_SMEM>>>(
                hgh, hgl, hgh, hgl,
                bt0h, bt0l, bt1h, bt1l,
                p1a, p1b, p1ah, p1al, p1bh, p1bl, 1);
            mma_gemm_dual<<<gg, 256, MMA_SMEM>>>(
                p1ah, p1al, p1bh, p1bl,
                bt0h, bt0l, bt1h, bt1l,
                p2a, p2b, p1ah, p1al, p1bh, p1bl, 0);

            combine_kernel<<<dim3(2, Cout, BB), 128>>>(
                hg, p1a, p2a, p1b, p2b, hcur, hnext,
                gcn_w + (size_t)i*32*160, gcn_b + (size_t)i*32,
                bn_g + (size_t)i*32, bn_b + (size_t)i*32,
                Cout, Cin);

            float* tmp = hcur; hcur = hnext; hnext = tmp;
        }
        Cin = Cout;
    }

    cudaStreamWaitEvent(0, evSkip, 0);   // all skip contributions in
    end1_kernel<<<dim3(4, 512/8, BB), 128>>>(skip, e1w, e1b, e1);
    end2_kernel<<<dim3(4, 12,  BB), 128>>>(e1, e2w, e2b, out);
}

// round 13
// speedup vs baseline: 1.0520x; 1.0520x over previous
#include <cuda_runtime.h>
#include <cuda_bf16.h>
#include <math.h>

#define BB   8
#define CH   32
#define NN   500
#define TT0  256
#define SCC  256

#define MAXELEM (BB*CH*TT0*NN)   // 32,768,000 floats
#define SROWS   32768            // max GEMM rows (layer 0: 8*32*128)
#define SW      512              // padded K width for bf16 splits

__device__ float g_h0[MAXELEM];
__device__ float g_h1[MAXELEM];
__device__ float g_hg[MAXELEM/2];
__device__ float g_p1a[MAXELEM/2];
__device__ float g_p2a[MAXELEM/2];
__device__ float g_p1b[MAXELEM/2];
__device__ float g_p2b[MAXELEM/2];
__device__ float g_skip[BB*SCC*NN];
__device__ float g_e1[BB*512*NN];

// bf16 split buffers; row width SW=512. Pad cols 500..511 are NEVER written and
// __device__ globals are zero-initialized, so they stay zero across graph replays.
__device__ __nv_bfloat16 g_hg_hi [SROWS*SW];
__device__ __nv_bfloat16 g_hg_lo [SROWS*SW];
__device__ __nv_bfloat16 g_p1a_hi[SROWS*SW];
__device__ __nv_bfloat16 g_p1a_lo[SROWS*SW];
__device__ __nv_bfloat16 g_p1b_hi[SROWS*SW];
__device__ __nv_bfloat16 g_p1b_lo[SROWS*SW];
// transposed+split adjacencies: Bt[n][k] = Adj[k][n], 512x512 (pads stay zero)
__device__ __nv_bfloat16 g_bt0_hi[SW*SW];
__device__ __nv_bfloat16 g_bt0_lo[SW*SW];
__device__ __nv_bfloat16 g_bt1_hi[SW*SW];
__device__ __nv_bfloat16 g_bt1_lo[SW*SW];

typedef unsigned long long u64;
typedef unsigned int u32;

__device__ __forceinline__ u64 pack_dup(float a){
    u64 r; unsigned ai = __float_as_uint(a);
    asm("mov.b64 %0, {%1, %1};" : "=l"(r) : "r"(ai));
    return r;
}
__device__ __forceinline__ void fma2(u64 &acc, u64 a, u64 b){
    asm("fma.rn.f32x2 %0, %1, %2, %0;" : "+l"(acc) : "l"(a), "l"(b));
}
__device__ __forceinline__ float2 unpack2(u64 v){
    unsigned lo, hi;
    asm("mov.b64 {%0, %1}, %2;" : "=r"(lo), "=r"(hi) : "l"(v));
    return make_float2(__uint_as_float(lo), __uint_as_float(hi));
}

// ---------------- PTX helpers: cp.async + ldmatrix + mma (all plain sm_80+) ----
__device__ __forceinline__ u32 smem_u32(const void* p){
    u32 a; asm("{ .reg .u64 t; cvta.to.shared.u64 t, %1; cvt.u32.u64 %0, t; }" : "=r"(a) : "l"(p));
    return a;
}
__device__ __forceinline__ void cp16(u32 s, const void* g){
    asm volatile("cp.async.cg.shared.global [%0], [%1], 16;" :: "r"(s), "l"(g));
}
__device__ __forceinline__ void cp_commit(){ asm volatile("cp.async.commit_group;" ::: "memory"); }
template<int N> __device__ __forceinline__ void cp_wait(){ asm volatile("cp.async.wait_group %0;" :: "n"(N) : "memory"); }

__device__ __forceinline__ void ldsm4(u32* r, u32 addr){
    asm volatile("ldmatrix.sync.aligned.m8n8.x4.shared.b16 {%0,%1,%2,%3}, [%4];"
        : "=r"(r[0]), "=r"(r[1]), "=r"(r[2]), "=r"(r[3]) : "r"(addr));
}
__device__ __forceinline__ void mma16816(float* d, const u32* a, u32 b0, u32 b1){
    asm volatile(
        "mma.sync.aligned.m16n8k16.row.col.f32.bf16.bf16.f32 "
        "{%0,%1,%2,%3}, {%4,%5,%6,%7}, {%8,%9}, {%0,%1,%2,%3};"
        : "+f"(d[0]), "+f"(d[1]), "+f"(d[2]), "+f"(d[3])
        : "r"(a[0]), "r"(a[1]), "r"(a[2]), "r"(a[3]), "r"(b0), "r"(b1));
}

// ---------------------------------------------------------------------------
// prep: block r (0..499) does BOTH
//   (a) bt0[.][r] = split(A0[r][.])           (transpose of A0)
//   (b) adp row r = softmax(relu(nv1@nv2))[r]; bt1[.][r] = split(adp[r][.])
// ---------------------------------------------------------------------------
__global__ void __launch_bounds__(512) prep_kernel(
    const float* __restrict__ A0,
    const float* __restrict__ nv1, const float* __restrict__ nv2,
    __nv_bfloat16* __restrict__ b0h, __nv_bfloat16* __restrict__ b0l,
    __nv_bfloat16* __restrict__ b1h, __nv_bfloat16* __restrict__ b1l)
{
    __shared__ float sv[NN];
    __shared__ float sred[16];
    __shared__ float sres;
    int r = blockIdx.x, tid = threadIdx.x;

    for (int j = tid; j < NN; j += 512){
        float v = A0[(size_t)r*NN + j];
        __nv_bfloat16 h = __float2bfloat16(v);
        __nv_bfloat16 l = __float2bfloat16(v - __bfloat162float(h));
        b0h[(size_t)j*SW + r] = h;
        b0l[(size_t)j*SW + r] = l;
    }

    float e1[10];
    #pragma unroll
    for (int k = 0; k < 10; k++) e1[k] = nv1[r*10 + k];

    float lmax = -1e30f;
    for (int j = tid; j < NN; j += 512){
        float v = 0.f;
        #pragma unroll
        for (int k = 0; k < 10; k++) v += e1[k] * nv2[k*NN + j];
        v = fmaxf(v, 0.f);
        sv[j] = v;
        lmax = fmaxf(lmax, v);
    }
    #pragma unroll
    for (int off = 16; off; off >>= 1) lmax = fmaxf(lmax, __shfl_xor_sync(0xffffffffu, lmax, off));
    if ((tid & 31) == 0) sred[tid >> 5] = lmax;
    __syncthreads();
    if (tid < 16){
        float v = sred[tid];
        #pragma unroll
        for (int off = 8; off; off >>= 1) v = fmaxf(v, __shfl_xor_sync(0xffffu, v, off));
        if (tid == 0) sres = v;
    }
    __syncthreads();
    float bmax = sres;
    float lsum = 0.f;
    for (int j = tid; j < NN; j += 512){
        float e = expf(sv[j] - bmax);
        sv[j] = e;
        lsum += e;
    }
    #pragma unroll
    for (int off = 16; off; off >>= 1) lsum += __shfl_xor_sync(0xffffffffu, lsum, off);
    __syncthreads();
    if ((tid & 31) == 0) sred[tid >> 5] = lsum;
    __syncthreads();
    if (tid < 16){
        float v = sred[tid];
        #pragma unroll
        for (int off = 8; off; off >>= 1) v += __shfl_xor_sync(0xffffu, v, off);
        if (tid == 0) sres = v;
    }
    __syncthreads();
    float inv = 1.0f / sres;
    for (int j = tid; j < NN; j += 512){
        float v = sv[j] * inv;
        __nv_bfloat16 h = __float2bfloat16(v);
        __nv_bfloat16 l = __float2bfloat16(v - __bfloat162float(h));
        b1h[(size_t)j*SW + r] = h;
        b1l[(size_t)j*SW + r] = l;
    }
}

// ---------------------------------------------------------------------------
// start conv (coalesced transpose): x [B,2,N,T] -> c0 [B,32,256,N], slot=255-t
// 32x32 (t,n) tiles staged through smem; reads coalesced over t, writes over n.
// ---------------------------------------------------------------------------
__global__ void __launch_bounds__(256) start_conv_kernel(
    const float* __restrict__ x, const float* __restrict__ w,
    const float* __restrict__ bias, float* __restrict__ h)
{
    __shared__ float xs0[32][33], xs1[32][33];
    __shared__ float wv[64], bv[32];
    int t0 = blockIdx.x*32, n0 = blockIdx.y*32, b = blockIdx.z;
    int tx = threadIdx.x & 31, ty = threadIdx.x >> 5;   // ty 0..7
    if (threadIdx.x < 64) wv[threadIdx.x] = w[threadIdx.x];
    if (threadIdx.x < 32) bv[threadIdx.x] = bias[threadIdx.x];

    #pragma unroll
    for (int r = 0; r < 4; r++){
        int nl = ty + r*8;
        int n = n0 + nl;
        float v0 = 0.f, v1 = 0.f;
        if (n < NN){
            v0 = x[((size_t)(b*2 + 0)*NN + n)*TT0 + t0 + tx];
            v1 = x[((size_t)(b*2 + 1)*NN + n)*TT0 + t0 + tx];
        }
        xs0[tx][nl] = v0;   // [t_local][n_local]
        xs1[tx][nl] = v1;
    }
    __syncthreads();

    int n = n0 + tx;
    bool ok = (n < NN);
    #pragma unroll
    for (int p = 0; p < 4; p++){
        int tl = ty + p*8;
        int slot = TT0 - 1 - (t0 + tl);
        float x0 = xs0[tl][tx], x1 = xs1[tl][tx];
        if (ok){
            #pragma unroll
            for (int o = 0; o < 32; o++){
                h[((size_t)(b*32 + o)*TT0 + slot)*NN + n] = wv[o*2]*x0 + wv[o*2+1]*x1 + bv[o];
            }
        }
    }
}

// ---------------------------------------------------------------------------
// gated dilated conv on COMPACT slots; also emits bf16 split of hg
// ---------------------------------------------------------------------------
__global__ void __launch_bounds__(128) gated_conv_kernel(
    const float* __restrict__ c, float* __restrict__ hg,
    __nv_bfloat16* __restrict__ hgh, __nv_bfloat16* __restrict__ hgl,
    const float* __restrict__ fw, const float* __restrict__ fb,
    const float* __restrict__ gw, const float* __restrict__ gb,
    int Cin, int Cout)
{
    __shared__ __align__(16) u64 wpk[32][32][4];
    int tid = threadIdx.x;
    for (int idx = tid; idx < 32*32; idx += 128){
        int cc = idx >> 5, o = idx & 31;
        wpk[cc][o][0] = pack_dup(fw[(o*32 + cc)*2 + 0]);
        wpk[cc][o][1] = pack_dup(fw[(o*32 + cc)*2 + 1]);
        wpk[cc][o][2] = pack_dup(gw[(o*32 + cc)*2 + 0]);
        wpk[cc][o][3] = pack_dup(gw[(o*32 + cc)*2 + 1]);
    }
    __syncthreads();
    int b = blockIdx.z, m = blockIdx.y;
    int n = (blockIdx.x*128 + tid)*2;
    if (n >= NN) return;

    const float* base0 = c + ((size_t)(b*32)*Cin + 2*m + 1)*NN + n;
    const float* base1 = c + ((size_t)(b*32)*Cin + 2*m)*NN + n;
    size_t cs = (size_t)Cin*NN;

    #pragma unroll 1
    for (int half = 0; half < 2; half++){
        u64 accf[16], accg[16];
        #pragma unroll
        for (int oo = 0; oo < 16; oo++){ accf[oo] = 0ull; accg[oo] = 0ull; }
        for (int cc = 0; cc < 32; cc++){
            u64 in0 = *(const u64*)(base0 + cc*cs);
            u64 in1 = *(const u64*)(base1 + cc*cs);
            const u64* wp = &wpk[cc][half*16][0];
            #pragma unroll
            for (int oo = 0; oo < 16; oo++){
                ulonglong2 wA = *(const ulonglong2*)(wp + oo*4);
                ulonglong2 wB = *(const ulonglong2*)(wp + oo*4 + 2);
                fma2(accf[oo], wA.x, in0);
                fma2(accf[oo], wA.y, in1);
                fma2(accg[oo], wB.x, in0);
                fma2(accg[oo], wB.y, in1);
            }
        }
        #pragma unroll
        for (int oo = 0; oo < 16; oo++){
            int o = half*16 + oo;
            float2 f = unpack2(accf[oo]);
            float2 g = unpack2(accg[oo]);
            float fbv = fb[o], gbv = gb[o];
            float2 out;
            out.x = tanhf(f.x + fbv) * (1.0f/(1.0f + expf(-(g.x + gbv))));
            out.y = tanhf(f.y + fbv) * (1.0f/(1.0f + expf(-(g.y + gbv))));
            size_t row = (size_t)(b*32 + o)*Cout + m;
            *(float2*)(hg + row*NN + n) = out;
            __nv_bfloat162 hv, lv;
            hv.x = __float2bfloat16(out.x);
            lv.x = __float2bfloat16(out.x - __bfloat162float(hv.x));
            hv.y = __float2bfloat16(out.y);
            lv.y = __float2bfloat16(out.y - __bfloat162float(hv.y));
            *(__nv_bfloat162*)(hgh + row*SW + n) = hv;
            *(__nv_bfloat162*)(hgl + row*SW + n) = lv;
        }
    }
}

// ---------------------------------------------------------------------------
// skip: slot 0 of hg is the last time index; 8 output channels per block
// ---------------------------------------------------------------------------
__global__ void __launch_bounds__(128) skip_kernel(
    const float* __restrict__ hg, const float* __restrict__ sw,
    const float* __restrict__ sb, float* __restrict__ skip,
    int Cout, int first)
{
    __shared__ __align__(16) float ws[32*8];    // ws[c*8+j] = sw[(o0+j)*32+c]
    int o0 = blockIdx.y*8, b = blockIdx.z, tid = threadIdx.x;
    for (int i = tid; i < 32*8; i += 128){
        int c = i >> 3, j = i & 7;
        ws[i] = sw[(o0 + j)*32 + c];
    }
    __syncthreads();
    int n = blockIdx.x*128 + tid;
    if (n >= NN) return;
    const float* p = hg + ((size_t)(b*32)*Cout)*NN + n;
    size_t cs = (size_t)Cout*NN;
    float acc[8];
    #pragma unroll
    for (int j = 0; j < 8; j++) acc[j] = sb[o0 + j];
    #pragma unroll
    for (int c = 0; c < 32; c++){
        float v = p[c*cs];
        float4 w0 = *(const float4*)&ws[c*8];
        float4 w1 = *(const float4*)&ws[c*8 + 4];
        acc[0] += w0.x*v; acc[1] += w0.y*v; acc[2] += w0.z*v; acc[3] += w0.w*v;
        acc[4] += w1.x*v; acc[5] += w1.y*v; acc[6] += w1.z*v; acc[7] += w1.w*v;
    }
    #pragma unroll
    for (int j = 0; j < 8; j++){
        float* dst = skip + ((size_t)b*SCC + o0 + j)*NN + n;
        if (first) *dst = acc[j];
        else       *dst += acc[j];
    }
}

// ---------------------------------------------------------------------------
// DUAL bf16 HMMA GEMM, 8 warps, 64x128 CTA tile, 3 CTAs/SM, ONE sync/chunk.
// Identical to the proven R11 kernel (295us, tensor 58%).
// ---------------------------------------------------------------------------
__global__ void __launch_bounds__(256, 3) mma_gemm_dual(
    const __nv_bfloat16* __restrict__ Ah0, const __nv_bfloat16* __restrict__ Al0,
    const __nv_bfloat16* __restrict__ Ah1, const __nv_bfloat16* __restrict__ Al1,
    const __nv_bfloat16* __restrict__ Bh0, const __nv_bfloat16* __restrict__ Bl0,
    const __nv_bfloat16* __restrict__ Bh1, const __nv_bfloat16* __restrict__ Bl1,
    float* __restrict__ C0, float* __restrict__ C1,
    __nv_bfloat16* __restrict__ Ch0, __nv_bfloat16* __restrict__ Cl0,
    __nv_bfloat16* __restrict__ Ch1, __nv_bfloat16* __restrict__ Cl1,
    int write_split)
{
    extern __shared__ __align__(128) char smem[];   // 3 x 24576 bytes
    const u32 sb = smem_u32(smem);
    const int tid = threadIdx.x;
    const int wid = tid >> 5, lane = tid & 31;
    const int wm = wid >> 2, wn = wid & 3;          // 2x4 warp grid, 32x32 tiles
    const int m0 = blockIdx.x << 6, n0 = blockIdx.y << 7;
    const int z = blockIdx.z;

    const __nv_bfloat16* Ahi = z ? Ah1 : Ah0;
    const __nv_bfloat16* Alo = z ? Al1 : Al0;
    const __nv_bfloat16* Bhi = z ? Bh1 : Bh0;
    const __nv_bfloat16* Blo = z ? Bl1 : Bl0;
    float* C = z ? C1 : C0;
    __nv_bfloat16* Chi = z ? Ch1 : Ch0;
    __nv_bfloat16* Clo = z ? Cl1 : Cl0;

    float acc[2][4][4];
    #pragma unroll
    for (int mt = 0; mt < 2; mt++)
        #pragma unroll
        for (int nt = 0; nt < 4; nt++)
            #pragma unroll
            for (int r = 0; r < 4; r++) acc[mt][nt][r] = 0.f;

    const __nv_bfloat16* baseAh = Ahi + (size_t)m0*SW;
    const __nv_bfloat16* baseAl = Alo + (size_t)m0*SW;
    const __nv_bfloat16* baseBh = Bhi + (size_t)n0*SW;
    const __nv_bfloat16* baseBl = Blo + (size_t)n0*SW;

    const int fr = tid >> 2, fc = tid & 3;
    const int fr2 = fr + 64;
    const u32 fdA  = (u32)(fr*64  + (fc ^ ((fr  >> 1) & 3))*16);
    const u32 fdB2 = (u32)(fr2*64 + (fc ^ ((fr2 >> 1) & 3))*16);
    const size_t fsA  = (size_t)fr*SW  + fc*8;
    const size_t fsB2 = (size_t)fr2*SW + fc*8;

    #define FILL(kc, bufaddr) do {                                   \
        size_t ko = (size_t)(kc)*32;                                 \
        cp16((bufaddr) +     0 + fdA,  baseAh + fsA  + ko);          \
        cp16((bufaddr) +  4096 + fdA,  baseAl + fsA  + ko);          \
        cp16((bufaddr) +  8192 + fdA,  baseBh + fsA  + ko);          \
        cp16((bufaddr) +  8192 + fdB2, baseBh + fsB2 + ko);          \
        cp16((bufaddr) + 16384 + fdA,  baseBl + fsA  + ko);          \
        cp16((bufaddr) + 16384 + fdB2, baseBl + fsB2 + ko);          \
        cp_commit();                                                 \
    } while(0)

    FILL(0, sb);
    FILL(1, sb + 24576);

    int st = 0;  // stage index of current chunk
    #pragma unroll 1
    for (int kc = 0; kc < 16; kc++){
        u32 cur = sb + (u32)st*24576;
        if (kc + 1 < 16) cp_wait<1>();
        else             cp_wait<0>();
        __syncthreads();                 // all warps done with stage (st-1)%3
        if (kc + 2 < 16){
            int ns = st + 2; if (ns >= 3) ns -= 3;
            FILL(kc + 2, sb + (u32)ns*24576);
        }

        #pragma unroll
        for (int ks = 0; ks < 2; ks++){
            u32 ah[2][4], al[2][4], bh[2][4], bl[2][4];
            #pragma unroll
            for (int mt = 0; mt < 2; mt++){
                int row = wm*32 + mt*16 + (lane & 15);
                int c = ks*2 + (lane >> 4);
                int csw = c ^ ((row >> 1) & 3);
                u32 a = cur + (u32)(row*64 + csw*16);
                ldsm4(ah[mt], a);
                ldsm4(al[mt], a + 4096);
            }
            #pragma unroll
            for (int np = 0; np < 2; np++){
                int row = wn*32 + np*16 + (lane & 7) + ((lane >> 4) << 3);
                int c = ks*2 + ((lane >> 3) & 1);
                int csw = c ^ ((row >> 1) & 3);
                u32 a = cur + (u32)(8192 + row*64 + csw*16);
                ldsm4(bh[np], a);
                ldsm4(bl[np], a + 8192);
            }
            #pragma unroll
            for (int mt = 0; mt < 2; mt++)
                #pragma unroll
                for (int nt = 0; nt < 4; nt++){
                    u32 b0h = bh[nt >> 1][(nt & 1)*2], b1h = bh[nt >> 1][(nt & 1)*2 + 1];
                    u32 b0l = bl[nt >> 1][(nt & 1)*2], b1l = bl[nt >> 1][(nt & 1)*2 + 1];
                    mma16816(acc[mt][nt], ah[mt], b0h, b1h);
                    mma16816(acc[mt][nt], ah[mt], b0l, b1l);
                    mma16816(acc[mt][nt], al[mt], b0h, b1h);
                }
        }
        st++; if (st >= 3) st -= 3;
    }
    #undef FILL

    // epilogue: c0=C[g][2t], c1=C[g][2t+1], c2=C[g+8][2t], c3=C[g+8][2t+1]
    int g = lane >> 2, t = lane & 3;
    #pragma unroll
    for (int mt = 0; mt < 2; mt++){
        #pragma unroll
        for (int nt = 0; nt < 4; nt++){
            int col = n0 + wn*32 + nt*8 + 2*t;
            if (col >= NN) continue;
            int row = m0 + wm*32 + mt*16 + g;
            float* d = acc[mt][nt];
            *(float2*)(C + (size_t)row*NN + col)       = make_float2(d[0], d[1]);
            *(float2*)(C + (size_t)(row + 8)*NN + col) = make_float2(d[2], d[3]);
            if (write_split){
                __nv_bfloat162 hv, lv;
                hv.x = __float2bfloat16(d[0]);
                lv.x = __float2bfloat16(d[0] - __bfloat162float(hv.x));
                hv.y = __float2bfloat16(d[1]);
                lv.y = __float2bfloat16(d[1] - __bfloat162float(hv.y));
                *(__nv_bfloat162*)(Chi + (size_t)row*SW + col) = hv;
                *(__nv_bfloat162*)(Clo + (size_t)row*SW + col) = lv;
                hv.x = __float2bfloat16(d[2]);
                lv.x = __float2bfloat16(d[2] - __bfloat162float(hv.x));
                hv.y = __float2bfloat16(d[3]);
                lv.y = __float2bfloat16(d[3] - __bfloat162float(hv.y));
                *(__nv_bfloat162*)(Chi + (size_t)(row + 8)*SW + col) = hv;
                *(__nv_bfloat162*)(Clo + (size_t)(row + 8)*SW + col) = lv;
            }
        }
    }
}

// ---------------------------------------------------------------------------
// combine on COMPACT slots
// ---------------------------------------------------------------------------
__global__ void __launch_bounds__(128) combine_kernel(
    const float* __restrict__ hg,  const float* __restrict__ p1a,
    const float* __restrict__ p2a, const float* __restrict__ p1b,
    const float* __restrict__ p2b, const float* __restrict__ res,
    float* __restrict__ hout,
    const float* __restrict__ gw,  const float* __restrict__ gb,
    const float* __restrict__ bng, const float* __restrict__ bnb,
    int Cout, int Cin)
{
    __shared__ __align__(16) u64 wpk[160][32];
    int tid = threadIdx.x;
    for (int idx = tid; idx < 160*32; idx += 128){
        int c = idx >> 5, o = idx & 31;
        wpk[c][o] = pack_dup(gw[o*160 + c]);
    }
    __syncthreads();
    int b = blockIdx.z, m = blockIdx.y;
    int n = (blockIdx.x*128 + tid)*2;
    if (n >= NN) return;

    u64 acc[32];
    #pragma unroll
    for (int o = 0; o < 32; o++) acc[o] = 0ull;

    size_t pt = ((size_t)(b*32)*Cout + m)*NN + n;
    size_t cs = (size_t)Cout*NN;
    #pragma unroll 1
    for (int s5 = 0; s5 < 5; s5++){
        const float* p = (s5 == 0 ? hg : s5 == 1 ? p1a : s5 == 2 ? p2a : s5 == 3 ? p1b : p2b) + pt;
        for (int cc = 0; cc < 32; cc++){
            u64 in = *(const u64*)(p + cc*cs);
            const u64* w = &wpk[s5*32 + cc][0];
            #pragma unroll
            for (int j = 0; j < 16; j++){
                ulonglong2 wv = *(const ulonglong2*)(w + 2*j);
                fma2(acc[2*j],   wv.x, in);
                fma2(acc[2*j+1], wv.y, in);
            }
        }
    }
    const float invs = 1.0f / sqrtf(1.0f + 1e-5f);
    #pragma unroll
    for (int o = 0; o < 32; o++){
        float2 a = unpack2(acc[o]);
        float2 r = *(const float2*)(res + ((size_t)(b*32 + o)*Cin + 2*m)*NN + n);
        float sc = bng[o]*invs, bbv = bnb[o], gbv = gb[o];
        float2 out;
        out.x = (a.x + gbv + r.x)*sc + bbv;
        out.y = (a.y + gbv + r.y)*sc + bbv;
        *(float2*)(hout + ((size_t)(b*32 + o)*Cout + m)*NN + n) = out;
    }
}

// ---------------------------------------------------------------------------
// end convs (T=1): end1 8 outputs/block, end2 4 outputs/block
// ---------------------------------------------------------------------------
__global__ void __launch_bounds__(128) end1_kernel(
    const float* __restrict__ sk, const float* __restrict__ w,
    const float* __restrict__ b1, float* __restrict__ e1)
{
    __shared__ __align__(16) float ws[256*8];   // ws[c*8+j] = w[(o0+j)*256+c]
    int o0 = blockIdx.y*8, b = blockIdx.z, tid = threadIdx.x;
    for (int i = tid; i < 256*8; i += 128){
        int c = i >> 3, j = i & 7;
        ws[i] = w[(o0 + j)*256 + c];
    }
    __syncthreads();
    int n = blockIdx.x*128 + tid;
    if (n >= NN) return;
    float acc[8];
    #pragma unroll
    for (int j = 0; j < 8; j++) acc[j] = b1[o0 + j];
    const float* sp = sk + (size_t)b*SCC*NN + n;
    #pragma unroll 4
    for (int c = 0; c < 256; c++){
        float v = fmaxf(sp[(size_t)c*NN], 0.f);
        float4 w0 = *(const float4*)&ws[c*8];
        float4 w1 = *(const float4*)&ws[c*8 + 4];
        acc[0] += w0.x*v; acc[1] += w0.y*v; acc[2] += w0.z*v; acc[3] += w0.w*v;
        acc[4] += w1.x*v; acc[5] += w1.y*v; acc[6] += w1.z*v; acc[7] += w1.w*v;
    }
    #pragma unroll
    for (int j = 0; j < 8; j++)
        e1[((size_t)b*512 + o0 + j)*NN + n] = fmaxf(acc[j], 0.f);
}

__global__ void __launch_bounds__(128) end2_kernel(
    const float* __restrict__ e1g, const float* __restrict__ w,
    const float* __restrict__ b2, float* __restrict__ out)
{
    __shared__ __align__(16) float ws[512*4];   // ws[c*4+j] = w[(o0+j)*512+c]
    int o0 = blockIdx.y*4, b = blockIdx.z, tid = threadIdx.x;
    for (int i = tid; i < 512*4; i += 128){
        int c = i >> 2, j = i & 3;
        ws[i] = w[(o0 + j)*512 + c];
    }
    __syncthreads();
    int n = blockIdx.x*128 + tid;
    if (n >= NN) return;
    float acc[4];
    #pragma unroll
    for (int j = 0; j < 4; j++) acc[j] = b2[o0 + j];
    const float* p = e1g + (size_t)b*512*NN + n;
    #pragma unroll 4
    for (int c = 0; c < 512; c++){
        float v = p[(size_t)c*NN];
        float4 w4 = *(const float4*)&ws[c*4];
        acc[0] += w4.x*v; acc[1] += w4.y*v; acc[2] += w4.z*v; acc[3] += w4.w*v;
    }
    #pragma unroll
    for (int j = 0; j < 4; j++)
        out[((size_t)b*12 + o0 + j)*NN + n] = acc[j];
}

// ---------------------------------------------------------------------------
extern "C" void kernel_launch(void* const* d_in, const int* in_sizes, int n_in,
                              void* d_out, int out_size)
{
    const float* x       = (const float*)d_in[0];
    const float* A0      = (const float*)d_in[1];
    const float* start_w = (const float*)d_in[2];
    const float* start_b = (const float*)d_in[3];
    const float* filt_w  = (const float*)d_in[4];
    const float* filt_b  = (const float*)d_in[5];
    const float* gate_w  = (const float*)d_in[6];
    const float* gate_b  = (const float*)d_in[7];
    const float* skip_w  = (const float*)d_in[8];
    const float* skip_b  = (const float*)d_in[9];
    const float* gcn_w   = (const float*)d_in[10];
    const float* gcn_b   = (const float*)d_in[11];
    const float* bn_g    = (const float*)d_in[12];
    const float* bn_b    = (const float*)d_in[13];
    const float* nv1     = (const float*)d_in[14];
    const float* nv2     = (const float*)d_in[15];
    const float* e1w     = (const float*)d_in[16];
    const float* e1b     = (const float*)d_in[17];
    const float* e2w     = (const float*)d_in[18];
    const float* e2b     = (const float*)d_in[19];
    float* out = (float*)d_out;

    float *h0, *h1, *hg, *p1a, *p2a, *p1b, *p2b, *skip, *e1;
    __nv_bfloat16 *hgh, *hgl, *p1ah, *p1al, *p1bh, *p1bl;
    __nv_bfloat16 *bt0h, *bt0l, *bt1h, *bt1l;
    cudaGetSymbolAddress((void**)&h0,  g_h0);
    cudaGetSymbolAddress((void**)&h1,  g_h1);
    cudaGetSymbolAddress((void**)&hg,  g_hg);
    cudaGetSymbolAddress((void**)&p1a, g_p1a);
    cudaGetSymbolAddress((void**)&p2a, g_p2a);
    cudaGetSymbolAddress((void**)&p1b, g_p1b);
    cudaGetSymbolAddress((void**)&p2b, g_p2b);
    cudaGetSymbolAddress((void**)&skip, g_skip);
    cudaGetSymbolAddress((void**)&e1,  g_e1);
    cudaGetSymbolAddress((void**)&hgh,  g_hg_hi);
    cudaGetSymbolAddress((void**)&hgl,  g_hg_lo);
    cudaGetSymbolAddress((void**)&p1ah, g_p1a_hi);
    cudaGetSymbolAddress((void**)&p1al, g_p1a_lo);
    cudaGetSymbolAddress((void**)&p1bh, g_p1b_hi);
    cudaGetSymbolAddress((void**)&p1bl, g_p1b_lo);
    cudaGetSymbolAddress((void**)&bt0h, g_bt0_hi);
    cudaGetSymbolAddress((void**)&bt0l, g_bt0_lo);
    cudaGetSymbolAddress((void**)&bt1h, g_bt1_hi);
    cudaGetSymbolAddress((void**)&bt1l, g_bt1_lo);

    const int MMA_SMEM = 3*24576;
    cudaFuncSetAttribute(mma_gemm_dual, cudaFuncAttributeMaxDynamicSharedMemorySize, MMA_SMEM);

    // launch order keeps the layer-0 dual GEMM in ncu's profiled slot
    start_conv_kernel<<<dim3(TT0/32, (NN + 31)/32, BB), 256>>>(x, start_w, start_b, h0);

    int Cin = TT0;
    float* hcur = h0;
    float* hnext = h1;
    for (int i = 0; i < 8; i++){
        int Cout = Cin >> 1;

        gated_conv_kernel<<<dim3(2, Cout, BB), 128>>>(
            hcur, hg, hgh, hgl,
            filt_w + (size_t)i*32*32*2, filt_b + (size_t)i*32,
            gate_w + (size_t)i*32*32*2, gate_b + (size_t)i*32,
            Cin, Cout);

        if (i == 0)
            prep_kernel<<<NN, 512>>>(A0, nv1, nv2, bt0h, bt0l, bt1h, bt1l);

        if (i < 7){
            int M = BB*CH*Cout;
            dim3 gg(M >> 6, 4, 2);
            // hop 1: p1a = hg@A0^T (z=0), p1b = hg@adp^T (z=1); chained splits
            mma_gemm_dual<<<gg, 256, MMA_SMEM>>>(
                hgh, hgl, hgh, hgl,
                bt0h, bt0l, bt1h, bt1l,
                p1a, p1b, p1ah, p1al, p1bh, p1bl, 1);
            // hop 2: p2a = p1a@A0^T (z=0), p2b = p1b@adp^T (z=1)
            mma_gemm_dual<<<gg, 256, MMA_SMEM>>>(
                p1ah, p1al, p1bh, p1bl,
                bt0h, bt0l, bt1h, bt1l,
                p2a, p2b, p1ah, p1al, p1bh, p1bl, 0);
        }

        skip_kernel<<<dim3(4, SCC/8, BB), 128>>>(
            hg, skip_w + (size_t)i*SCC*32, skip_b + (size_t)i*SCC,
            skip, Cout, (i == 0) ? 1 : 0);

        if (i < 7){
            combine_kernel<<<dim3(2, Cout, BB), 128>>>(
                hg, p1a, p2a, p1b, p2b, hcur, hnext,
                gcn_w + (size_t)i*32*160, gcn_b + (size_t)i*32,
                bn_g + (size_t)i*32, bn_b + (size_t)i*32,
                Cout, Cin);

            float* tmp = hcur; hcur = hnext; hnext = tmp;
        }
        Cin = Cout;
    }

    end1_kernel<<<dim3(4, 512/8, BB), 128>>>(skip, e1w, e1b, e1);
    end2_kernel<<<dim3(4, 12/4, BB), 128>>>(e1, e2w, e2b, out);
}

// round 14
// speedup vs baseline: 1.1155x; 1.0604x over previous
#include <cuda_runtime.h>
#include <cuda_bf16.h>
#include <math.h>

#define BB   8
#define CH   32
#define NN   500
#define TT0  256
#define SCC  256

#define MAXELEM (BB*CH*TT0*NN)   // 32,768,000 floats
#define SROWS   32768            // max GEMM rows (layer 0: 8*32*128)
#define SW      512              // padded K width for bf16 splits

__device__ float g_h0[MAXELEM];
__device__ float g_h1[MAXELEM];
__device__ float g_hg[MAXELEM/2];
__device__ float g_p1a[MAXELEM/2];
__device__ float g_p2a[MAXELEM/2];
__device__ float g_p1b[MAXELEM/2];
__device__ float g_p2b[MAXELEM/2];
__device__ float g_skip[BB*SCC*NN];
__device__ float g_e1[BB*512*NN];

// bf16 split buffers; row width SW=512. Pad cols 500..511 are NEVER written and
// __device__ globals are zero-initialized, so they stay zero across graph replays.
__device__ __nv_bfloat16 g_hg_hi [SROWS*SW];
__device__ __nv_bfloat16 g_hg_lo [SROWS*SW];
// transposed splits: bt[n][k] = Adj[k][n]; row-major splits: ar[k][v] = Adj[k][v]
__device__ __nv_bfloat16 g_bt0_hi[SW*SW];
__device__ __nv_bfloat16 g_bt0_lo[SW*SW];
__device__ __nv_bfloat16 g_bt1_hi[SW*SW];
__device__ __nv_bfloat16 g_bt1_lo[SW*SW];
__device__ __nv_bfloat16 g_a0r_hi[SW*SW];
__device__ __nv_bfloat16 g_a0r_lo[SW*SW];
__device__ __nv_bfloat16 g_a1r_hi[SW*SW];
__device__ __nv_bfloat16 g_a1r_lo[SW*SW];
// transposed splits of the SQUARED adjacencies: bts[n][k] = (Adj^2)[k][n]
__device__ __nv_bfloat16 g_bt0s_hi[SW*SW];
__device__ __nv_bfloat16 g_bt0s_lo[SW*SW];
__device__ __nv_bfloat16 g_bt1s_hi[SW*SW];
__device__ __nv_bfloat16 g_bt1s_lo[SW*SW];

typedef unsigned long long u64;
typedef unsigned int u32;

__device__ __forceinline__ u64 pack_dup(float a){
    u64 r; unsigned ai = __float_as_uint(a);
    asm("mov.b64 %0, {%1, %1};" : "=l"(r) : "r"(ai));
    return r;
}
__device__ __forceinline__ void fma2(u64 &acc, u64 a, u64 b){
    asm("fma.rn.f32x2 %0, %1, %2, %0;" : "+l"(acc) : "l"(a), "l"(b));
}
__device__ __forceinline__ float2 unpack2(u64 v){
    unsigned lo, hi;
    asm("mov.b64 {%0, %1}, %2;" : "=r"(lo), "=r"(hi) : "l"(v));
    return make_float2(__uint_as_float(lo), __uint_as_float(hi));
}

// ---------------- PTX helpers: cp.async + ldmatrix + mma (all plain sm_80+) ----
__device__ __forceinline__ u32 smem_u32(const void* p){
    u32 a; asm("{ .reg .u64 t; cvta.to.shared.u64 t, %1; cvt.u32.u64 %0, t; }" : "=r"(a) : "l"(p));
    return a;
}
__device__ __forceinline__ void cp16(u32 s, const void* g){
    asm volatile("cp.async.cg.shared.global [%0], [%1], 16;" :: "r"(s), "l"(g));
}
__device__ __forceinline__ void cp_commit(){ asm volatile("cp.async.commit_group;" ::: "memory"); }
template<int N> __device__ __forceinline__ void cp_wait(){ asm volatile("cp.async.wait_group %0;" :: "n"(N) : "memory"); }

__device__ __forceinline__ void ldsm4(u32* r, u32 addr){
    asm volatile("ldmatrix.sync.aligned.m8n8.x4.shared.b16 {%0,%1,%2,%3}, [%4];"
        : "=r"(r[0]), "=r"(r[1]), "=r"(r[2]), "=r"(r[3]) : "r"(addr));
}
__device__ __forceinline__ void mma16816(float* d, const u32* a, u32 b0, u32 b1){
    asm volatile(
        "mma.sync.aligned.m16n8k16.row.col.f32.bf16.bf16.f32 "
        "{%0,%1,%2,%3}, {%4,%5,%6,%7}, {%8,%9}, {%0,%1,%2,%3};"
        : "+f"(d[0]), "+f"(d[1]), "+f"(d[2]), "+f"(d[3])
        : "r"(a[0]), "r"(a[1]), "r"(a[2]), "r"(a[3]), "r"(b0), "r"(b1));
}

// ---------------------------------------------------------------------------
// prep: block r (0..499) writes, for A0 and adp row r:
//   transposed split bt[.][r] and row-major split ar[r][.]
// ---------------------------------------------------------------------------
__global__ void __launch_bounds__(512) prep_kernel(
    const float* __restrict__ A0,
    const float* __restrict__ nv1, const float* __restrict__ nv2,
    __nv_bfloat16* __restrict__ b0h, __nv_bfloat16* __restrict__ b0l,
    __nv_bfloat16* __restrict__ b1h, __nv_bfloat16* __restrict__ b1l,
    __nv_bfloat16* __restrict__ a0h, __nv_bfloat16* __restrict__ a0l,
    __nv_bfloat16* __restrict__ a1h, __nv_bfloat16* __restrict__ a1l)
{
    __shared__ float sv[NN];
    __shared__ float sred[16];
    __shared__ float sres;
    int r = blockIdx.x, tid = threadIdx.x;

    for (int j = tid; j < NN; j += 512){
        float v = A0[(size_t)r*NN + j];
        __nv_bfloat16 h = __float2bfloat16(v);
        __nv_bfloat16 l = __float2bfloat16(v - __bfloat162float(h));
        b0h[(size_t)j*SW + r] = h;
        b0l[(size_t)j*SW + r] = l;
        a0h[(size_t)r*SW + j] = h;
        a0l[(size_t)r*SW + j] = l;
    }

    float e1[10];
    #pragma unroll
    for (int k = 0; k < 10; k++) e1[k] = nv1[r*10 + k];

    float lmax = -1e30f;
    for (int j = tid; j < NN; j += 512){
        float v = 0.f;
        #pragma unroll
        for (int k = 0; k < 10; k++) v += e1[k] * nv2[k*NN + j];
        v = fmaxf(v, 0.f);
        sv[j] = v;
        lmax = fmaxf(lmax, v);
    }
    #pragma unroll
    for (int off = 16; off; off >>= 1) lmax = fmaxf(lmax, __shfl_xor_sync(0xffffffffu, lmax, off));
    if ((tid & 31) == 0) sred[tid >> 5] = lmax;
    __syncthreads();
    if (tid < 16){
        float v = sred[tid];
        #pragma unroll
        for (int off = 8; off; off >>= 1) v = fmaxf(v, __shfl_xor_sync(0xffffu, v, off));
        if (tid == 0) sres = v;
    }
    __syncthreads();
    float bmax = sres;
    float lsum = 0.f;
    for (int j = tid; j < NN; j += 512){
        float e = expf(sv[j] - bmax);
        sv[j] = e;
        lsum += e;
    }
    #pragma unroll
    for (int off = 16; off; off >>= 1) lsum += __shfl_xor_sync(0xffffffffu, lsum, off);
    __syncthreads();
    if ((tid & 31) == 0) sred[tid >> 5] = lsum;
    __syncthreads();
    if (tid < 16){
        float v = sred[tid];
        #pragma unroll
        for (int off = 8; off; off >>= 1) v += __shfl_xor_sync(0xffffu, v, off);
        if (tid == 0) sres = v;
    }
    __syncthreads();
    float inv = 1.0f / sres;
    for (int j = tid; j < NN; j += 512){
        float v = sv[j] * inv;
        __nv_bfloat16 h = __float2bfloat16(v);
        __nv_bfloat16 l = __float2bfloat16(v - __bfloat162float(h));
        b1h[(size_t)j*SW + r] = h;
        b1l[(size_t)j*SW + r] = l;
        a1h[(size_t)r*SW + j] = h;
        a1l[(size_t)r*SW + j] = l;
    }
}

// ---------------------------------------------------------------------------
// start conv (coalesced transpose): x [B,2,N,T] -> c0 [B,32,256,N], slot=255-t
// ---------------------------------------------------------------------------
__global__ void __launch_bounds__(256) start_conv_kernel(
    const float* __restrict__ x, const float* __restrict__ w,
    const float* __restrict__ bias, float* __restrict__ h)
{
    __shared__ float xs0[32][33], xs1[32][33];
    __shared__ float wv[64], bv[32];
    int t0 = blockIdx.x*32, n0 = blockIdx.y*32, b = blockIdx.z;
    int tx = threadIdx.x & 31, ty = threadIdx.x >> 5;   // ty 0..7
    if (threadIdx.x < 64) wv[threadIdx.x] = w[threadIdx.x];
    if (threadIdx.x < 32) bv[threadIdx.x] = bias[threadIdx.x];

    #pragma unroll
    for (int r = 0; r < 4; r++){
        int nl = ty + r*8;
        int n = n0 + nl;
        float v0 = 0.f, v1 = 0.f;
        if (n < NN){
            v0 = x[((size_t)(b*2 + 0)*NN + n)*TT0 + t0 + tx];
            v1 = x[((size_t)(b*2 + 1)*NN + n)*TT0 + t0 + tx];
        }
        xs0[tx][nl] = v0;
        xs1[tx][nl] = v1;
    }
    __syncthreads();

    int n = n0 + tx;
    bool ok = (n < NN);
    #pragma unroll
    for (int p = 0; p < 4; p++){
        int tl = ty + p*8;
        int slot = TT0 - 1 - (t0 + tl);
        float x0 = xs0[tl][tx], x1 = xs1[tl][tx];
        if (ok){
            #pragma unroll
            for (int o = 0; o < 32; o++){
                h[((size_t)(b*32 + o)*TT0 + slot)*NN + n] = wv[o*2]*x0 + wv[o*2+1]*x1 + bv[o];
            }
        }
    }
}

// ---------------------------------------------------------------------------
// gated dilated conv on COMPACT slots; also emits bf16 split of hg
// ---------------------------------------------------------------------------
__global__ void __launch_bounds__(128) gated_conv_kernel(
    const float* __restrict__ c, float* __restrict__ hg,
    __nv_bfloat16* __restrict__ hgh, __nv_bfloat16* __restrict__ hgl,
    const float* __restrict__ fw, const float* __restrict__ fb,
    const float* __restrict__ gw, const float* __restrict__ gb,
    int Cin, int Cout)
{
    __shared__ __align__(16) u64 wpk[32][32][4];
    int tid = threadIdx.x;
    for (int idx = tid; idx < 32*32; idx += 128){
        int cc = idx >> 5, o = idx & 31;
        wpk[cc][o][0] = pack_dup(fw[(o*32 + cc)*2 + 0]);
        wpk[cc][o][1] = pack_dup(fw[(o*32 + cc)*2 + 1]);
        wpk[cc][o][2] = pack_dup(gw[(o*32 + cc)*2 + 0]);
        wpk[cc][o][3] = pack_dup(gw[(o*32 + cc)*2 + 1]);
    }
    __syncthreads();
    int b = blockIdx.z, m = blockIdx.y;
    int n = (blockIdx.x*128 + tid)*2;
    if (n >= NN) return;

    const float* base0 = c + ((size_t)(b*32)*Cin + 2*m + 1)*NN + n;
    const float* base1 = c + ((size_t)(b*32)*Cin + 2*m)*NN + n;
    size_t cs = (size_t)Cin*NN;

    #pragma unroll 1
    for (int half = 0; half < 2; half++){
        u64 accf[16], accg[16];
        #pragma unroll
        for (int oo = 0; oo < 16; oo++){ accf[oo] = 0ull; accg[oo] = 0ull; }
        for (int cc = 0; cc < 32; cc++){
            u64 in0 = *(const u64*)(base0 + cc*cs);
            u64 in1 = *(const u64*)(base1 + cc*cs);
            const u64* wp = &wpk[cc][half*16][0];
            #pragma unroll
            for (int oo = 0; oo < 16; oo++){
                ulonglong2 wA = *(const ulonglong2*)(wp + oo*4);
                ulonglong2 wB = *(const ulonglong2*)(wp + oo*4 + 2);
                fma2(accf[oo], wA.x, in0);
                fma2(accf[oo], wA.y, in1);
                fma2(accg[oo], wB.x, in0);
                fma2(accg[oo], wB.y, in1);
            }
        }
        #pragma unroll
        for (int oo = 0; oo < 16; oo++){
            int o = half*16 + oo;
            float2 f = unpack2(accf[oo]);
            float2 g = unpack2(accg[oo]);
            float fbv = fb[o], gbv = gb[o];
            float2 out;
            out.x = tanhf(f.x + fbv) * (1.0f/(1.0f + expf(-(g.x + gbv))));
            out.y = tanhf(f.y + fbv) * (1.0f/(1.0f + expf(-(g.y + gbv))));
            size_t row = (size_t)(b*32 + o)*Cout + m;
            *(float2*)(hg + row*NN + n) = out;
            __nv_bfloat162 hv, lv;
            hv.x = __float2bfloat16(out.x);
            lv.x = __float2bfloat16(out.x - __bfloat162float(hv.x));
            hv.y = __float2bfloat16(out.y);
            lv.y = __float2bfloat16(out.y - __bfloat162float(hv.y));
            *(__nv_bfloat162*)(hgh + row*SW + n) = hv;
            *(__nv_bfloat162*)(hgl + row*SW + n) = lv;
        }
    }
}

// ---------------------------------------------------------------------------
// skip: slot 0 of hg is the last time index; 8 output channels per block
// ---------------------------------------------------------------------------
__global__ void __launch_bounds__(128) skip_kernel(
    const float* __restrict__ hg, const float* __restrict__ sw,
    const float* __restrict__ sb, float* __restrict__ skip,
    int Cout, int first)
{
    __shared__ __align__(16) float ws[32*8];
    int o0 = blockIdx.y*8, b = blockIdx.z, tid = threadIdx.x;
    for (int i = tid; i < 32*8; i += 128){
        int c = i >> 3, j = i & 7;
        ws[i] = sw[(o0 + j)*32 + c];
    }
    __syncthreads();
    int n = blockIdx.x*128 + tid;
    if (n >= NN) return;
    const float* p = hg + ((size_t)(b*32)*Cout)*NN + n;
    size_t cs = (size_t)Cout*NN;
    float acc[8];
    #pragma unroll
    for (int j = 0; j < 8; j++) acc[j] = sb[o0 + j];
    #pragma unroll
    for (int c = 0; c < 32; c++){
        float v = p[c*cs];
        float4 w0 = *(const float4*)&ws[c*8];
        float4 w1 = *(const float4*)&ws[c*8 + 4];
        acc[0] += w0.x*v; acc[1] += w0.y*v; acc[2] += w0.z*v; acc[3] += w0.w*v;
        acc[4] += w1.x*v; acc[5] += w1.y*v; acc[6] += w1.z*v; acc[7] += w1.w*v;
    }
    #pragma unroll
    for (int j = 0; j < 8; j++){
        float* dst = skip + ((size_t)b*SCC + o0 + j)*NN + n;
        if (first) *dst = acc[j];
        else       *dst += acc[j];
    }
}

// ---------------------------------------------------------------------------
// DUAL bf16 HMMA GEMM (R11-proven core), used for adjacency squaring with
// write_split=1: emits the transposed split of the result directly.
// ---------------------------------------------------------------------------
__global__ void __launch_bounds__(256, 3) mma_gemm_dual(
    const __nv_bfloat16* __restrict__ Ah0, const __nv_bfloat16* __restrict__ Al0,
    const __nv_bfloat16* __restrict__ Ah1, const __nv_bfloat16* __restrict__ Al1,
    const __nv_bfloat16* __restrict__ Bh0, const __nv_bfloat16* __restrict__ Bl0,
    const __nv_bfloat16* __restrict__ Bh1, const __nv_bfloat16* __restrict__ Bl1,
    float* __restrict__ C0, float* __restrict__ C1,
    __nv_bfloat16* __restrict__ Ch0, __nv_bfloat16* __restrict__ Cl0,
    __nv_bfloat16* __restrict__ Ch1, __nv_bfloat16* __restrict__ Cl1,
    int write_split)
{
    extern __shared__ __align__(128) char smem[];
    const u32 sb = smem_u32(smem);
    const int tid = threadIdx.x;
    const int wid = tid >> 5, lane = tid & 31;
    const int wm = wid >> 2, wn = wid & 3;
    const int m0 = blockIdx.x << 6, n0 = blockIdx.y << 7;
    const int z = blockIdx.z;

    const __nv_bfloat16* Ahi = z ? Ah1 : Ah0;
    const __nv_bfloat16* Alo = z ? Al1 : Al0;
    const __nv_bfloat16* Bhi = z ? Bh1 : Bh0;
    const __nv_bfloat16* Blo = z ? Bl1 : Bl0;
    float* C = z ? C1 : C0;
    __nv_bfloat16* Chi = z ? Ch1 : Ch0;
    __nv_bfloat16* Clo = z ? Cl1 : Cl0;

    float acc[2][4][4];
    #pragma unroll
    for (int mt = 0; mt < 2; mt++)
        #pragma unroll
        for (int nt = 0; nt < 4; nt++)
            #pragma unroll
            for (int r = 0; r < 4; r++) acc[mt][nt][r] = 0.f;

    const __nv_bfloat16* baseAh = Ahi + (size_t)m0*SW;
    const __nv_bfloat16* baseAl = Alo + (size_t)m0*SW;
    const __nv_bfloat16* baseBh = Bhi + (size_t)n0*SW;
    const __nv_bfloat16* baseBl = Blo + (size_t)n0*SW;

    const int fr = tid >> 2, fc = tid & 3;
    const int fr2 = fr + 64;
    const u32 fdA  = (u32)(fr*64  + (fc ^ ((fr  >> 1) & 3))*16);
    const u32 fdB2 = (u32)(fr2*64 + (fc ^ ((fr2 >> 1) & 3))*16);
    const size_t fsA  = (size_t)fr*SW  + fc*8;
    const size_t fsB2 = (size_t)fr2*SW + fc*8;

    #define FILL(kc, bufaddr) do {                                   \
        size_t ko = (size_t)(kc)*32;                                 \
        cp16((bufaddr) +     0 + fdA,  baseAh + fsA  + ko);          \
        cp16((bufaddr) +  4096 + fdA,  baseAl + fsA  + ko);          \
        cp16((bufaddr) +  8192 + fdA,  baseBh + fsA  + ko);          \
        cp16((bufaddr) +  8192 + fdB2, baseBh + fsB2 + ko);          \
        cp16((bufaddr) + 16384 + fdA,  baseBl + fsA  + ko);          \
        cp16((bufaddr) + 16384 + fdB2, baseBl + fsB2 + ko);          \
        cp_commit();                                                 \
    } while(0)

    FILL(0, sb);
    FILL(1, sb + 24576);

    int st = 0;
    #pragma unroll 1
    for (int kc = 0; kc < 16; kc++){
        u32 cur = sb + (u32)st*24576;
        if (kc + 1 < 16) cp_wait<1>();
        else             cp_wait<0>();
        __syncthreads();
        if (kc + 2 < 16){
            int ns = st + 2; if (ns >= 3) ns -= 3;
            FILL(kc + 2, sb + (u32)ns*24576);
        }

        #pragma unroll
        for (int ks = 0; ks < 2; ks++){
            u32 ah[2][4], al[2][4], bh[2][4], bl[2][4];
            #pragma unroll
            for (int mt = 0; mt < 2; mt++){
                int row = wm*32 + mt*16 + (lane & 15);
                int c = ks*2 + (lane >> 4);
                int csw = c ^ ((row >> 1) & 3);
                u32 a = cur + (u32)(row*64 + csw*16);
                ldsm4(ah[mt], a);
                ldsm4(al[mt], a + 4096);
            }
            #pragma unroll
            for (int np = 0; np < 2; np++){
                int row = wn*32 + np*16 + (lane & 7) + ((lane >> 4) << 3);
                int c = ks*2 + ((lane >> 3) & 1);
                int csw = c ^ ((row >> 1) & 3);
                u32 a = cur + (u32)(8192 + row*64 + csw*16);
                ldsm4(bh[np], a);
                ldsm4(bl[np], a + 8192);
            }
            #pragma unroll
            for (int mt = 0; mt < 2; mt++)
                #pragma unroll
                for (int nt = 0; nt < 4; nt++){
                    u32 b0h = bh[nt >> 1][(nt & 1)*2], b1h = bh[nt >> 1][(nt & 1)*2 + 1];
                    u32 b0l = bl[nt >> 1][(nt & 1)*2], b1l = bl[nt >> 1][(nt & 1)*2 + 1];
                    mma16816(acc[mt][nt], ah[mt], b0h, b1h);
                    mma16816(acc[mt][nt], ah[mt], b0l, b1l);
                    mma16816(acc[mt][nt], al[mt], b0h, b1h);
                }
        }
        st++; if (st >= 3) st -= 3;
    }
    #undef FILL

    int g = lane >> 2, t = lane & 3;
    #pragma unroll
    for (int mt = 0; mt < 2; mt++){
        #pragma unroll
        for (int nt = 0; nt < 4; nt++){
            int col = n0 + wn*32 + nt*8 + 2*t;
            if (col >= NN) continue;
            int row = m0 + wm*32 + mt*16 + g;
            float* d = acc[mt][nt];
            *(float2*)(C + (size_t)row*NN + col)       = make_float2(d[0], d[1]);
            *(float2*)(C + (size_t)(row + 8)*NN + col) = make_float2(d[2], d[3]);
            if (write_split){
                __nv_bfloat162 hv, lv;
                hv.x = __float2bfloat16(d[0]);
                lv.x = __float2bfloat16(d[0] - __bfloat162float(hv.x));
                hv.y = __float2bfloat16(d[1]);
                lv.y = __float2bfloat16(d[1] - __bfloat162float(hv.y));
                *(__nv_bfloat162*)(Chi + (size_t)row*SW + col) = hv;
                *(__nv_bfloat162*)(Clo + (size_t)row*SW + col) = lv;
                hv.x = __float2bfloat16(d[2]);
                lv.x = __float2bfloat16(d[2] - __bfloat162float(hv.x));
                hv.y = __float2bfloat16(d[3]);
                lv.y = __float2bfloat16(d[3] - __bfloat162float(hv.y));
                *(__nv_bfloat162*)(Chi + (size_t)(row + 8)*SW + col) = hv;
                *(__nv_bfloat162*)(Clo + (size_t)(row + 8)*SW + col) = lv;
            }
        }
    }
}

// ---------------------------------------------------------------------------
// QUAD bf16 HMMA GEMM: z in {0..3} selects B operand / output; A is always
// the hg split. Same proven core, no split-write.
// z=0: p1a = hg@A0, z=1: p1b = hg@adp, z=2: p2a = hg@A0^2, z=3: p2b = hg@adp^2
// ---------------------------------------------------------------------------
__global__ void __launch_bounds__(256, 3) mma_gemm_quad(
    const __nv_bfloat16* __restrict__ Ah, const __nv_bfloat16* __restrict__ Al,
    const __nv_bfloat16* __restrict__ B0h, const __nv_bfloat16* __restrict__ B0l,
    const __nv_bfloat16* __restrict__ B1h, const __nv_bfloat16* __restrict__ B1l,
    const __nv_bfloat16* __restrict__ B2h, const __nv_bfloat16* __restrict__ B2l,
    const __nv_bfloat16* __restrict__ B3h, const __nv_bfloat16* __restrict__ B3l,
    float* __restrict__ C0, float* __restrict__ C1,
    float* __restrict__ C2, float* __restrict__ C3)
{
    extern __shared__ __align__(128) char smem[];
    const u32 sb = smem_u32(smem);
    const int tid = threadIdx.x;
    const int wid = tid >> 5, lane = tid & 31;
    const int wm = wid >> 2, wn = wid & 3;
    const int m0 = blockIdx.x << 6, n0 = blockIdx.y << 7;
    const int z = blockIdx.z;

    const __nv_bfloat16* Bhi = (z == 0) ? B0h : (z == 1) ? B1h : (z == 2) ? B2h : B3h;
    const __nv_bfloat16* Blo = (z == 0) ? B0l : (z == 1) ? B1l : (z == 2) ? B2l : B3l;
    float* C = (z == 0) ? C0 : (z == 1) ? C1 : (z == 2) ? C2 : C3;

    float acc[2][4][4];
    #pragma unroll
    for (int mt = 0; mt < 2; mt++)
        #pragma unroll
        for (int nt = 0; nt < 4; nt++)
            #pragma unroll
            for (int r = 0; r < 4; r++) acc[mt][nt][r] = 0.f;

    const __nv_bfloat16* baseAh = Ah + (size_t)m0*SW;
    const __nv_bfloat16* baseAl = Al + (size_t)m0*SW;
    const __nv_bfloat16* baseBh = Bhi + (size_t)n0*SW;
    const __nv_bfloat16* baseBl = Blo + (size_t)n0*SW;

    const int fr = tid >> 2, fc = tid & 3;
    const int fr2 = fr + 64;
    const u32 fdA  = (u32)(fr*64  + (fc ^ ((fr  >> 1) & 3))*16);
    const u32 fdB2 = (u32)(fr2*64 + (fc ^ ((fr2 >> 1) & 3))*16);
    const size_t fsA  = (size_t)fr*SW  + fc*8;
    const size_t fsB2 = (size_t)fr2*SW + fc*8;

    #define FILL(kc, bufaddr) do {                                   \
        size_t ko = (size_t)(kc)*32;                                 \
        cp16((bufaddr) +     0 + fdA,  baseAh + fsA  + ko);          \
        cp16((bufaddr) +  4096 + fdA,  baseAl + fsA  + ko);          \
        cp16((bufaddr) +  8192 + fdA,  baseBh + fsA  + ko);          \
        cp16((bufaddr) +  8192 + fdB2, baseBh + fsB2 + ko);          \
        cp16((bufaddr) + 16384 + fdA,  baseBl + fsA  + ko);          \
        cp16((bufaddr) + 16384 + fdB2, baseBl + fsB2 + ko);          \
        cp_commit();                                                 \
    } while(0)

    FILL(0, sb);
    FILL(1, sb + 24576);

    int st = 0;
    #pragma unroll 1
    for (int kc = 0; kc < 16; kc++){
        u32 cur = sb + (u32)st*24576;
        if (kc + 1 < 16) cp_wait<1>();
        else             cp_wait<0>();
        __syncthreads();
        if (kc + 2 < 16){
            int ns = st + 2; if (ns >= 3) ns -= 3;
            FILL(kc + 2, sb + (u32)ns*24576);
        }

        #pragma unroll
        for (int ks = 0; ks < 2; ks++){
            u32 ah[2][4], al[2][4], bh[2][4], bl[2][4];
            #pragma unroll
            for (int mt = 0; mt < 2; mt++){
                int row = wm*32 + mt*16 + (lane & 15);
                int c = ks*2 + (lane >> 4);
                int csw = c ^ ((row >> 1) & 3);
                u32 a = cur + (u32)(row*64 + csw*16);
                ldsm4(ah[mt], a);
                ldsm4(al[mt], a + 4096);
            }
            #pragma unroll
            for (int np = 0; np < 2; np++){
                int row = wn*32 + np*16 + (lane & 7) + ((lane >> 4) << 3);
                int c = ks*2 + ((lane >> 3) & 1);
                int csw = c ^ ((row >> 1) & 3);
                u32 a = cur + (u32)(8192 + row*64 + csw*16);
                ldsm4(bh[np], a);
                ldsm4(bl[np], a + 8192);
            }
            #pragma unroll
            for (int mt = 0; mt < 2; mt++)
                #pragma unroll
                for (int nt = 0; nt < 4; nt++){
                    u32 b0h = bh[nt >> 1][(nt & 1)*2], b1h = bh[nt >> 1][(nt & 1)*2 + 1];
                    u32 b0l = bl[nt >> 1][(nt & 1)*2], b1l = bl[nt >> 1][(nt & 1)*2 + 1];
                    mma16816(acc[mt][nt], ah[mt], b0h, b1h);
                    mma16816(acc[mt][nt], ah[mt], b0l, b1l);
                    mma16816(acc[mt][nt], al[mt], b0h, b1h);
                }
        }
        st++; if (st >= 3) st -= 3;
    }
    #undef FILL

    int g = lane >> 2, t = lane & 3;
    #pragma unroll
    for (int mt = 0; mt < 2; mt++){
        #pragma unroll
        for (int nt = 0; nt < 4; nt++){
            int col = n0 + wn*32 + nt*8 + 2*t;
            if (col >= NN) continue;
            int row = m0 + wm*32 + mt*16 + g;
            float* d = acc[mt][nt];
            *(float2*)(C + (size_t)row*NN + col)       = make_float2(d[0], d[1]);
            *(float2*)(C + (size_t)(row + 8)*NN + col) = make_float2(d[2], d[3]);
        }
    }
}

// ---------------------------------------------------------------------------
// combine on COMPACT slots
// ---------------------------------------------------------------------------
__global__ void __launch_bounds__(128) combine_kernel(
    const float* __restrict__ hg,  const float* __restrict__ p1a,
    const float* __restrict__ p2a, const float* __restrict__ p1b,
    const float* __restrict__ p2b, const float* __restrict__ res,
    float* __restrict__ hout,
    const float* __restrict__ gw,  const float* __restrict__ gb,
    const float* __restrict__ bng, const float* __restrict__ bnb,
    int Cout, int Cin)
{
    __shared__ __align__(16) u64 wpk[160][32];
    int tid = threadIdx.x;
    for (int idx = tid; idx < 160*32; idx += 128){
        int c = idx >> 5, o = idx & 31;
        wpk[c][o] = pack_dup(gw[o*160 + c]);
    }
    __syncthreads();
    int b = blockIdx.z, m = blockIdx.y;
    int n = (blockIdx.x*128 + tid)*2;
    if (n >= NN) return;

    u64 acc[32];
    #pragma unroll
    for (int o = 0; o < 32; o++) acc[o] = 0ull;

    size_t pt = ((size_t)(b*32)*Cout + m)*NN + n;
    size_t cs = (size_t)Cout*NN;
    #pragma unroll 1
    for (int s5 = 0; s5 < 5; s5++){
        const float* p = (s5 == 0 ? hg : s5 == 1 ? p1a : s5 == 2 ? p2a : s5 == 3 ? p1b : p2b) + pt;
        for (int cc = 0; cc < 32; cc++){
            u64 in = *(const u64*)(p + cc*cs);
            const u64* w = &wpk[s5*32 + cc][0];
            #pragma unroll
            for (int j = 0; j < 16; j++){
                ulonglong2 wv = *(const ulonglong2*)(w + 2*j);
                fma2(acc[2*j],   wv.x, in);
                fma2(acc[2*j+1], wv.y, in);
            }
        }
    }
    const float invs = 1.0f / sqrtf(1.0f + 1e-5f);
    #pragma unroll
    for (int o = 0; o < 32; o++){
        float2 a = unpack2(acc[o]);
        float2 r = *(const float2*)(res + ((size_t)(b*32 + o)*Cin + 2*m)*NN + n);
        float sc = bng[o]*invs, bbv = bnb[o], gbv = gb[o];
        float2 out;
        out.x = (a.x + gbv + r.x)*sc + bbv;
        out.y = (a.y + gbv + r.y)*sc + bbv;
        *(float2*)(hout + ((size_t)(b*32 + o)*Cout + m)*NN + n) = out;
    }
}

// ---------------------------------------------------------------------------
// end convs (T=1): end1 8 outputs/block, end2 4 outputs/block
// ---------------------------------------------------------------------------
__global__ void __launch_bounds__(128) end1_kernel(
    const float* __restrict__ sk, const float* __restrict__ w,
    const float* __restrict__ b1, float* __restrict__ e1)
{
    __shared__ __align__(16) float ws[256*8];
    int o0 = blockIdx.y*8, b = blockIdx.z, tid = threadIdx.x;
    for (int i = tid; i < 256*8; i += 128){
        int c = i >> 3, j = i & 7;
        ws[i] = w[(o0 + j)*256 + c];
    }
    __syncthreads();
    int n = blockIdx.x*128 + tid;
    if (n >= NN) return;
    float acc[8];
    #pragma unroll
    for (int j = 0; j < 8; j++) acc[j] = b1[o0 + j];
    const float* sp = sk + (size_t)b*SCC*NN + n;
    #pragma unroll 4
    for (int c = 0; c < 256; c++){
        float v = fmaxf(sp[(size_t)c*NN], 0.f);
        float4 w0 = *(const float4*)&ws[c*8];
        float4 w1 = *(const float4*)&ws[c*8 + 4];
        acc[0] += w0.x*v; acc[1] += w0.y*v; acc[2] += w0.z*v; acc[3] += w0.w*v;
        acc[4] += w1.x*v; acc[5] += w1.y*v; acc[6] += w1.z*v; acc[7] += w1.w*v;
    }
    #pragma unroll
    for (int j = 0; j < 8; j++)
        e1[((size_t)b*512 + o0 + j)*NN + n] = fmaxf(acc[j], 0.f);
}

__global__ void __launch_bounds__(128) end2_kernel(
    const float* __restrict__ e1g, const float* __restrict__ w,
    const float* __restrict__ b2, float* __restrict__ out)
{
    __shared__ __align__(16) float ws[512*4];
    int o0 = blockIdx.y*4, b = blockIdx.z, tid = threadIdx.x;
    for (int i = tid; i < 512*4; i += 128){
        int c = i >> 2, j = i & 3;
        ws[i] = w[(o0 + j)*512 + c];
    }
    __syncthreads();
    int n = blockIdx.x*128 + tid;
    if (n >= NN) return;
    float acc[4];
    #pragma unroll
    for (int j = 0; j < 4; j++) acc[j] = b2[o0 + j];
    const float* p = e1g + (size_t)b*512*NN + n;
    #pragma unroll 4
    for (int c = 0; c < 512; c++){
        float v = p[(size_t)c*NN];
        float4 w4 = *(const float4*)&ws[c*4];
        acc[0] += w4.x*v; acc[1] += w4.y*v; acc[2] += w4.z*v; acc[3] += w4.w*v;
    }
    #pragma unroll
    for (int j = 0; j < 4; j++)
        out[((size_t)b*12 + o0 + j)*NN + n] = acc[j];
}

// ---------------------------------------------------------------------------
extern "C" void kernel_launch(void* const* d_in, const int* in_sizes, int n_in,
                              void* d_out, int out_size)
{
    const float* x       = (const float*)d_in[0];
    const float* A0      = (const float*)d_in[1];
    const float* start_w = (const float*)d_in[2];
    const float* start_b = (const float*)d_in[3];
    const float* filt_w  = (const float*)d_in[4];
    const float* filt_b  = (const float*)d_in[5];
    const float* gate_w  = (const float*)d_in[6];
    const float* gate_b  = (const float*)d_in[7];
    const float* skip_w  = (const float*)d_in[8];
    const float* skip_b  = (const float*)d_in[9];
    const float* gcn_w   = (const float*)d_in[10];
    const float* gcn_b   = (const float*)d_in[11];
    const float* bn_g    = (const float*)d_in[12];
    const float* bn_b    = (const float*)d_in[13];
    const float* nv1     = (const float*)d_in[14];
    const float* nv2     = (const float*)d_in[15];
    const float* e1w     = (const float*)d_in[16];
    const float* e1b     = (const float*)d_in[17];
    const float* e2w     = (const float*)d_in[18];
    const float* e2b     = (const float*)d_in[19];
    float* out = (float*)d_out;

    float *h0, *h1, *hg, *p1a, *p2a, *p1b, *p2b, *skip, *e1;
    __nv_bfloat16 *hgh, *hgl;
    __nv_bfloat16 *bt0h, *bt0l, *bt1h, *bt1l;
    __nv_bfloat16 *a0rh, *a0rl, *a1rh, *a1rl;
    __nv_bfloat16 *bt0sh, *bt0sl, *bt1sh, *bt1sl;
    cudaGetSymbolAddress((void**)&h0,  g_h0);
    cudaGetSymbolAddress((void**)&h1,  g_h1);
    cudaGetSymbolAddress((void**)&hg,  g_hg);
    cudaGetSymbolAddress((void**)&p1a, g_p1a);
    cudaGetSymbolAddress((void**)&p2a, g_p2a);
    cudaGetSymbolAddress((void**)&p1b, g_p1b);
    cudaGetSymbolAddress((void**)&p2b, g_p2b);
    cudaGetSymbolAddress((void**)&skip, g_skip);
    cudaGetSymbolAddress((void**)&e1,  g_e1);
    cudaGetSymbolAddress((void**)&hgh,  g_hg_hi);
    cudaGetSymbolAddress((void**)&hgl,  g_hg_lo);
    cudaGetSymbolAddress((void**)&bt0h, g_bt0_hi);
    cudaGetSymbolAddress((void**)&bt0l, g_bt0_lo);
    cudaGetSymbolAddress((void**)&bt1h, g_bt1_hi);
    cudaGetSymbolAddress((void**)&bt1l, g_bt1_lo);
    cudaGetSymbolAddress((void**)&a0rh, g_a0r_hi);
    cudaGetSymbolAddress((void**)&a0rl, g_a0r_lo);
    cudaGetSymbolAddress((void**)&a1rh, g_a1r_hi);
    cudaGetSymbolAddress((void**)&a1rl, g_a1r_lo);
    cudaGetSymbolAddress((void**)&bt0sh, g_bt0s_hi);
    cudaGetSymbolAddress((void**)&bt0sl, g_bt0s_lo);
    cudaGetSymbolAddress((void**)&bt1sh, g_bt1s_hi);
    cudaGetSymbolAddress((void**)&bt1sl, g_bt1s_lo);

    const int MMA_SMEM = 3*24576;
    cudaFuncSetAttribute(mma_gemm_dual, cudaFuncAttributeMaxDynamicSharedMemorySize, MMA_SMEM);
    cudaFuncSetAttribute(mma_gemm_quad, cudaFuncAttributeMaxDynamicSharedMemorySize, MMA_SMEM);

    start_conv_kernel<<<dim3(TT0/32, (NN + 31)/32, BB), 256>>>(x, start_w, start_b, h0);

    int Cin = TT0;
    float* hcur = h0;
    float* hnext = h1;
    for (int i = 0; i < 8; i++){
        int Cout = Cin >> 1;

        gated_conv_kernel<<<dim3(2, Cout, BB), 128>>>(
            hcur, hg, hgh, hgl,
            filt_w + (size_t)i*32*32*2, filt_b + (size_t)i*32,
            gate_w + (size_t)i*32*32*2, gate_b + (size_t)i*32,
            Cin, Cout);

        if (i == 0){
            prep_kernel<<<NN, 512>>>(A0, nv1, nv2, bt0h, bt0l, bt1h, bt1l,
                                     a0rh, a0rl, a1rh, a1rl);
            // square the adjacencies: bt_s[n][k] = (Adj^2)[k][n]
            //   D[n][k] = sum_v bt[n][v] * Arow[k][v]; fp32 C goes to scratch
            mma_gemm_dual<<<dim3(8, 4, 2), 256, MMA_SMEM>>>(
                bt0h, bt0l, bt1h, bt1l,
                a0rh, a0rl, a1rh, a1rl,
                p2a, p2b,                    // fp32 scratch, overwritten later
                bt0sh, bt0sl, bt1sh, bt1sl, 1);
        }

        if (i < 7){
            int M = BB*CH*Cout;
            dim3 gg(M >> 6, 4, 4);
            mma_gemm_quad<<<gg, 256, MMA_SMEM>>>(
                hgh, hgl,
                bt0h, bt0l, bt1h, bt1l,
                bt0sh, bt0sl, bt1sh, bt1sl,
                p1a, p1b, p2a, p2b);
        }

        skip_kernel<<<dim3(4, SCC/8, BB), 128>>>(
            hg, skip_w + (size_t)i*SCC*32, skip_b + (size_t)i*SCC,
            skip, Cout, (i == 0) ? 1 : 0);

        if (i < 7){
            combine_kernel<<<dim3(2, Cout, BB), 128>>>(
                hg, p1a, p2a, p1b, p2b, hcur, hnext,
                gcn_w + (size_t)i*32*160, gcn_b + (size_t)i*32,
                bn_g + (size_t)i*32, bn_b + (size_t)i*32,
                Cout, Cin);

            float* tmp = hcur; hcur = hnext; hnext = tmp;
        }
        Cin = Cout;
    }

    end1_kernel<<<dim3(4, 512/8, BB), 128>>>(skip, e1w, e1b, e1);
    end2_kernel<<<dim3(4, 12/4, BB), 128>>>(e1, e2w, e2b, out);
}

// round 15
// speedup vs baseline: 1.1353x; 1.0177x over previous
#include <cuda_runtime.h>
#include <cuda_bf16.h>
#include <math.h>

#define BB   8
#define CH   32
#define NN   500
#define TT0  256
#define SCC  256

#define MAXELEM (BB*CH*TT0*NN)   // 32,768,000 floats
#define SROWS   32768            // max GEMM rows (layer 0: 8*32*128)
#define SW      512              // padded K width for bf16 splits

__device__ float g_h0[MAXELEM];
__device__ float g_h1[MAXELEM];
__device__ float g_hg[MAXELEM/2];
__device__ float g_p1a[MAXELEM/2];
__device__ float g_p2a[MAXELEM/2];
__device__ float g_p1b[MAXELEM/2];
__device__ float g_p2b[MAXELEM/2];
__device__ float g_skip[BB*SCC*NN];
__device__ float g_e1[BB*512*NN];

// bf16 split buffers; row width SW=512. Pad cols 500..511 are NEVER written and
// __device__ globals are zero-initialized, so they stay zero across graph replays.
__device__ __nv_bfloat16 g_hg_hi [SROWS*SW];
__device__ __nv_bfloat16 g_hg_lo [SROWS*SW];
// transposed splits: bt[n][k] = Adj[k][n]; row-major splits: ar[k][v] = Adj[k][v]
__device__ __nv_bfloat16 g_bt0_hi[SW*SW];
__device__ __nv_bfloat16 g_bt0_lo[SW*SW];
__device__ __nv_bfloat16 g_bt1_hi[SW*SW];
__device__ __nv_bfloat16 g_bt1_lo[SW*SW];
__device__ __nv_bfloat16 g_a0r_hi[SW*SW];
__device__ __nv_bfloat16 g_a0r_lo[SW*SW];
__device__ __nv_bfloat16 g_a1r_hi[SW*SW];
__device__ __nv_bfloat16 g_a1r_lo[SW*SW];
// transposed splits of the SQUARED adjacencies: bts[n][k] = (Adj^2)[k][n]
__device__ __nv_bfloat16 g_bt0s_hi[SW*SW];
__device__ __nv_bfloat16 g_bt0s_lo[SW*SW];
__device__ __nv_bfloat16 g_bt1s_hi[SW*SW];
__device__ __nv_bfloat16 g_bt1s_lo[SW*SW];

typedef unsigned long long u64;
typedef unsigned int u32;

__device__ __forceinline__ u64 pack_dup(float a){
    u64 r; unsigned ai = __float_as_uint(a);
    asm("mov.b64 %0, {%1, %1};" : "=l"(r) : "r"(ai));
    return r;
}
__device__ __forceinline__ void fma2(u64 &acc, u64 a, u64 b){
    asm("fma.rn.f32x2 %0, %1, %2, %0;" : "+l"(acc) : "l"(a), "l"(b));
}
__device__ __forceinline__ float2 unpack2(u64 v){
    unsigned lo, hi;
    asm("mov.b64 {%0, %1}, %2;" : "=r"(lo), "=r"(hi) : "l"(v));
    return make_float2(__uint_as_float(lo), __uint_as_float(hi));
}

// ---------------- PTX helpers: cp.async + ldmatrix + mma (all plain sm_80+) ----
__device__ __forceinline__ u32 smem_u32(const void* p){
    u32 a; asm("{ .reg .u64 t; cvta.to.shared.u64 t, %1; cvt.u32.u64 %0, t; }" : "=r"(a) : "l"(p));
    return a;
}
__device__ __forceinline__ void cp16(u32 s, const void* g){
    asm volatile("cp.async.cg.shared.global [%0], [%1], 16;" :: "r"(s), "l"(g));
}
__device__ __forceinline__ void cp_commit(){ asm volatile("cp.async.commit_group;" ::: "memory"); }
template<int N> __device__ __forceinline__ void cp_wait(){ asm volatile("cp.async.wait_group %0;" :: "n"(N) : "memory"); }

__device__ __forceinline__ void ldsm4(u32* r, u32 addr){
    asm volatile("ldmatrix.sync.aligned.m8n8.x4.shared.b16 {%0,%1,%2,%3}, [%4];"
        : "=r"(r[0]), "=r"(r[1]), "=r"(r[2]), "=r"(r[3]) : "r"(addr));
}
__device__ __forceinline__ void mma16816(float* d, const u32* a, u32 b0, u32 b1){
    asm volatile(
        "mma.sync.aligned.m16n8k16.row.col.f32.bf16.bf16.f32 "
        "{%0,%1,%2,%3}, {%4,%5,%6,%7}, {%8,%9}, {%0,%1,%2,%3};"
        : "+f"(d[0]), "+f"(d[1]), "+f"(d[2]), "+f"(d[3])
        : "r"(a[0]), "r"(a[1]), "r"(a[2]), "r"(a[3]), "r"(b0), "r"(b1));
}

// ---------------------------------------------------------------------------
// prep: block r (0..499) writes, for A0 and adp row r:
//   transposed split bt[.][r] and row-major split ar[r][.]
// ---------------------------------------------------------------------------
__global__ void __launch_bounds__(512) prep_kernel(
    const float* __restrict__ A0,
    const float* __restrict__ nv1, const float* __restrict__ nv2,
    __nv_bfloat16* __restrict__ b0h, __nv_bfloat16* __restrict__ b0l,
    __nv_bfloat16* __restrict__ b1h, __nv_bfloat16* __restrict__ b1l,
    __nv_bfloat16* __restrict__ a0h, __nv_bfloat16* __restrict__ a0l,
    __nv_bfloat16* __restrict__ a1h, __nv_bfloat16* __restrict__ a1l)
{
    __shared__ float sv[NN];
    __shared__ float sred[16];
    __shared__ float sres;
    int r = blockIdx.x, tid = threadIdx.x;

    for (int j = tid; j < NN; j += 512){
        float v = A0[(size_t)r*NN + j];
        __nv_bfloat16 h = __float2bfloat16(v);
        __nv_bfloat16 l = __float2bfloat16(v - __bfloat162float(h));
        b0h[(size_t)j*SW + r] = h;
        b0l[(size_t)j*SW + r] = l;
        a0h[(size_t)r*SW + j] = h;
        a0l[(size_t)r*SW + j] = l;
    }

    float e1[10];
    #pragma unroll
    for (int k = 0; k < 10; k++) e1[k] = nv1[r*10 + k];

    float lmax = -1e30f;
    for (int j = tid; j < NN; j += 512){
        float v = 0.f;
        #pragma unroll
        for (int k = 0; k < 10; k++) v += e1[k] * nv2[k*NN + j];
        v = fmaxf(v, 0.f);
        sv[j] = v;
        lmax = fmaxf(lmax, v);
    }
    #pragma unroll
    for (int off = 16; off; off >>= 1) lmax = fmaxf(lmax, __shfl_xor_sync(0xffffffffu, lmax, off));
    if ((tid & 31) == 0) sred[tid >> 5] = lmax;
    __syncthreads();
    if (tid < 16){
        float v = sred[tid];
        #pragma unroll
        for (int off = 8; off; off >>= 1) v = fmaxf(v, __shfl_xor_sync(0xffffu, v, off));
        if (tid == 0) sres = v;
    }
    __syncthreads();
    float bmax = sres;
    float lsum = 0.f;
    for (int j = tid; j < NN; j += 512){
        float e = expf(sv[j] - bmax);
        sv[j] = e;
        lsum += e;
    }
    #pragma unroll
    for (int off = 16; off; off >>= 1) lsum += __shfl_xor_sync(0xffffffffu, lsum, off);
    __syncthreads();
    if ((tid & 31) == 0) sred[tid >> 5] = lsum;
    __syncthreads();
    if (tid < 16){
        float v = sred[tid];
        #pragma unroll
        for (int off = 8; off; off >>= 1) v += __shfl_xor_sync(0xffffu, v, off);
        if (tid == 0) sres = v;
    }
    __syncthreads();
    float inv = 1.0f / sres;
    for (int j = tid; j < NN; j += 512){
        float v = sv[j] * inv;
        __nv_bfloat16 h = __float2bfloat16(v);
        __nv_bfloat16 l = __float2bfloat16(v - __bfloat162float(h));
        b1h[(size_t)j*SW + r] = h;
        b1l[(size_t)j*SW + r] = l;
        a1h[(size_t)r*SW + j] = h;
        a1l[(size_t)r*SW + j] = l;
    }
}

// ---------------------------------------------------------------------------
// start conv (coalesced transpose): x [B,2,N,T] -> c0 [B,32,256,N], slot=255-t
// ---------------------------------------------------------------------------
__global__ void __launch_bounds__(256) start_conv_kernel(
    const float* __restrict__ x, const float* __restrict__ w,
    const float* __restrict__ bias, float* __restrict__ h)
{
    __shared__ float xs0[32][33], xs1[32][33];
    __shared__ float wv[64], bv[32];
    int t0 = blockIdx.x*32, n0 = blockIdx.y*32, b = blockIdx.z;
    int tx = threadIdx.x & 31, ty = threadIdx.x >> 5;   // ty 0..7
    if (threadIdx.x < 64) wv[threadIdx.x] = w[threadIdx.x];
    if (threadIdx.x < 32) bv[threadIdx.x] = bias[threadIdx.x];

    #pragma unroll
    for (int r = 0; r < 4; r++){
        int nl = ty + r*8;
        int n = n0 + nl;
        float v0 = 0.f, v1 = 0.f;
        if (n < NN){
            v0 = x[((size_t)(b*2 + 0)*NN + n)*TT0 + t0 + tx];
            v1 = x[((size_t)(b*2 + 1)*NN + n)*TT0 + t0 + tx];
        }
        xs0[tx][nl] = v0;
        xs1[tx][nl] = v1;
    }
    __syncthreads();

    int n = n0 + tx;
    bool ok = (n < NN);
    #pragma unroll
    for (int p = 0; p < 4; p++){
        int tl = ty + p*8;
        int slot = TT0 - 1 - (t0 + tl);
        float x0 = xs0[tl][tx], x1 = xs1[tl][tx];
        if (ok){
            #pragma unroll
            for (int o = 0; o < 32; o++){
                h[((size_t)(b*32 + o)*TT0 + slot)*NN + n] = wv[o*2]*x0 + wv[o*2+1]*x1 + bv[o];
            }
        }
    }
}

// ---------------------------------------------------------------------------
// gated dilated conv on COMPACT slots; emits fp32 hg + bf16 split.
// 256 threads: tid 0-127 do output channels 0-15, 128-255 do 16-31;
// both groups load the same inputs concurrently (L1 broadcast) instead of
// the old serial half loop that re-issued every global load twice.
// ---------------------------------------------------------------------------
__global__ void __launch_bounds__(256) gated_conv_kernel(
    const float* __restrict__ c, float* __restrict__ hg,
    __nv_bfloat16* __restrict__ hgh, __nv_bfloat16* __restrict__ hgl,
    const float* __restrict__ fw, const float* __restrict__ fb,
    const float* __restrict__ gw, const float* __restrict__ gb,
    int Cin, int Cout)
{
    __shared__ __align__(16) u64 wpk[32][32][4];
    for (int idx = threadIdx.x; idx < 32*32; idx += 256){
        int cc = idx >> 5, o = idx & 31;
        wpk[cc][o][0] = pack_dup(fw[(o*32 + cc)*2 + 0]);
        wpk[cc][o][1] = pack_dup(fw[(o*32 + cc)*2 + 1]);
        wpk[cc][o][2] = pack_dup(gw[(o*32 + cc)*2 + 0]);
        wpk[cc][o][3] = pack_dup(gw[(o*32 + cc)*2 + 1]);
    }
    __syncthreads();
    int tid  = threadIdx.x & 127;
    int half = threadIdx.x >> 7;
    int b = blockIdx.z, m = blockIdx.y;
    int n = (blockIdx.x*128 + tid)*2;
    if (n >= NN) return;

    const float* base0 = c + ((size_t)(b*32)*Cin + 2*m + 1)*NN + n;
    const float* base1 = c + ((size_t)(b*32)*Cin + 2*m)*NN + n;
    size_t cs = (size_t)Cin*NN;

    u64 accf[16], accg[16];
    #pragma unroll
    for (int oo = 0; oo < 16; oo++){ accf[oo] = 0ull; accg[oo] = 0ull; }
    for (int cc = 0; cc < 32; cc++){
        u64 in0 = *(const u64*)(base0 + cc*cs);
        u64 in1 = *(const u64*)(base1 + cc*cs);
        const u64* wp = &wpk[cc][half*16][0];
        #pragma unroll
        for (int oo = 0; oo < 16; oo++){
            ulonglong2 wA = *(const ulonglong2*)(wp + oo*4);
            ulonglong2 wB = *(const ulonglong2*)(wp + oo*4 + 2);
            fma2(accf[oo], wA.x, in0);
            fma2(accf[oo], wA.y, in1);
            fma2(accg[oo], wB.x, in0);
            fma2(accg[oo], wB.y, in1);
        }
    }
    #pragma unroll
    for (int oo = 0; oo < 16; oo++){
        int o = half*16 + oo;
        float2 f = unpack2(accf[oo]);
        float2 g = unpack2(accg[oo]);
        float fbv = fb[o], gbv = gb[o];
        float2 out;
        out.x = tanhf(f.x + fbv) * (1.0f/(1.0f + expf(-(g.x + gbv))));
        out.y = tanhf(f.y + fbv) * (1.0f/(1.0f + expf(-(g.y + gbv))));
        size_t row = (size_t)(b*32 + o)*Cout + m;
        *(float2*)(hg + row*NN + n) = out;
        __nv_bfloat162 hv, lv;
        hv.x = __float2bfloat16(out.x);
        lv.x = __float2bfloat16(out.x - __bfloat162float(hv.x));
        hv.y = __float2bfloat16(out.y);
        lv.y = __float2bfloat16(out.y - __bfloat162float(hv.y));
        *(__nv_bfloat162*)(hgh + row*SW + n) = hv;
        *(__nv_bfloat162*)(hgl + row*SW + n) = lv;
    }
}

// ---------------------------------------------------------------------------
// skip: slot 0 of hg is the last time index; 8 output channels per block
// ---------------------------------------------------------------------------
__global__ void __launch_bounds__(128) skip_kernel(
    const float* __restrict__ hg, const float* __restrict__ sw,
    const float* __restrict__ sb, float* __restrict__ skip,
    int Cout, int first)
{
    __shared__ __align__(16) float ws[32*8];
    int o0 = blockIdx.y*8, b = blockIdx.z, tid = threadIdx.x;
    for (int i = tid; i < 32*8; i += 128){
        int c = i >> 3, j = i & 7;
        ws[i] = sw[(o0 + j)*32 + c];
    }
    __syncthreads();
    int n = blockIdx.x*128 + tid;
    if (n >= NN) return;
    const float* p = hg + ((size_t)(b*32)*Cout)*NN + n;
    size_t cs = (size_t)Cout*NN;
    float acc[8];
    #pragma unroll
    for (int j = 0; j < 8; j++) acc[j] = sb[o0 + j];
    #pragma unroll
    for (int c = 0; c < 32; c++){
        float v = p[c*cs];
        float4 w0 = *(const float4*)&ws[c*8];
        float4 w1 = *(const float4*)&ws[c*8 + 4];
        acc[0] += w0.x*v; acc[1] += w0.y*v; acc[2] += w0.z*v; acc[3] += w0.w*v;
        acc[4] += w1.x*v; acc[5] += w1.y*v; acc[6] += w1.z*v; acc[7] += w1.w*v;
    }
    #pragma unroll
    for (int j = 0; j < 8; j++){
        float* dst = skip + ((size_t)b*SCC + o0 + j)*NN + n;
        if (first) *dst = acc[j];
        else       *dst += acc[j];
    }
}

// ---------------------------------------------------------------------------
// DUAL bf16 HMMA GEMM (R11-proven core), used for adjacency squaring with
// write_split=1: emits the transposed split of the result directly.
// ---------------------------------------------------------------------------
__global__ void __launch_bounds__(256, 3) mma_gemm_dual(
    const __nv_bfloat16* __restrict__ Ah0, const __nv_bfloat16* __restrict__ Al0,
    const __nv_bfloat16* __restrict__ Ah1, const __nv_bfloat16* __restrict__ Al1,
    const __nv_bfloat16* __restrict__ Bh0, const __nv_bfloat16* __restrict__ Bl0,
    const __nv_bfloat16* __restrict__ Bh1, const __nv_bfloat16* __restrict__ Bl1,
    float* __restrict__ C0, float* __restrict__ C1,
    __nv_bfloat16* __restrict__ Ch0, __nv_bfloat16* __restrict__ Cl0,
    __nv_bfloat16* __restrict__ Ch1, __nv_bfloat16* __restrict__ Cl1,
    int write_split)
{
    extern __shared__ __align__(128) char smem[];
    const u32 sb = smem_u32(smem);
    const int tid = threadIdx.x;
    const int wid = tid >> 5, lane = tid & 31;
    const int wm = wid >> 2, wn = wid & 3;
    const int m0 = blockIdx.x << 6, n0 = blockIdx.y << 7;
    const int z = blockIdx.z;

    const __nv_bfloat16* Ahi = z ? Ah1 : Ah0;
    const __nv_bfloat16* Alo = z ? Al1 : Al0;
    const __nv_bfloat16* Bhi = z ? Bh1 : Bh0;
    const __nv_bfloat16* Blo = z ? Bl1 : Bl0;
    float* C = z ? C1 : C0;
    __nv_bfloat16* Chi = z ? Ch1 : Ch0;
    __nv_bfloat16* Clo = z ? Cl1 : Cl0;

    float acc[2][4][4];
    #pragma unroll
    for (int mt = 0; mt < 2; mt++)
        #pragma unroll
        for (int nt = 0; nt < 4; nt++)
            #pragma unroll
            for (int r = 0; r < 4; r++) acc[mt][nt][r] = 0.f;

    const __nv_bfloat16* baseAh = Ahi + (size_t)m0*SW;
    const __nv_bfloat16* baseAl = Alo + (size_t)m0*SW;
    const __nv_bfloat16* baseBh = Bhi + (size_t)n0*SW;
    const __nv_bfloat16* baseBl = Blo + (size_t)n0*SW;

    const int fr = tid >> 2, fc = tid & 3;
    const int fr2 = fr + 64;
    const u32 fdA  = (u32)(fr*64  + (fc ^ ((fr  >> 1) & 3))*16);
    const u32 fdB2 = (u32)(fr2*64 + (fc ^ ((fr2 >> 1) & 3))*16);
    const size_t fsA  = (size_t)fr*SW  + fc*8;
    const size_t fsB2 = (size_t)fr2*SW + fc*8;

    #define FILL(kc, bufaddr) do {                                   \
        size_t ko = (size_t)(kc)*32;                                 \
        cp16((bufaddr) +     0 + fdA,  baseAh + fsA  + ko);          \
        cp16((bufaddr) +  4096 + fdA,  baseAl + fsA  + ko);          \
        cp16((bufaddr) +  8192 + fdA,  baseBh + fsA  + ko);          \
        cp16((bufaddr) +  8192 + fdB2, baseBh + fsB2 + ko);          \
        cp16((bufaddr) + 16384 + fdA,  baseBl + fsA  + ko);          \
        cp16((bufaddr) + 16384 + fdB2, baseBl + fsB2 + ko);          \
        cp_commit();                                                 \
    } while(0)

    FILL(0, sb);
    FILL(1, sb + 24576);

    int st = 0;
    #pragma unroll 1
    for (int kc = 0; kc < 16; kc++){
        u32 cur = sb + (u32)st*24576;
        if (kc + 1 < 16) cp_wait<1>();
        else             cp_wait<0>();
        __syncthreads();
        if (kc + 2 < 16){
            int ns = st + 2; if (ns >= 3) ns -= 3;
            FILL(kc + 2, sb + (u32)ns*24576);
        }

        #pragma unroll
        for (int ks = 0; ks < 2; ks++){
            u32 ah[2][4], al[2][4], bh[2][4], bl[2][4];
            #pragma unroll
            for (int mt = 0; mt < 2; mt++){
                int row = wm*32 + mt*16 + (lane & 15);
                int c = ks*2 + (lane >> 4);
                int csw = c ^ ((row >> 1) & 3);
                u32 a = cur + (u32)(row*64 + csw*16);
                ldsm4(ah[mt], a);
                ldsm4(al[mt], a + 4096);
            }
            #pragma unroll
            for (int np = 0; np < 2; np++){
                int row = wn*32 + np*16 + (lane & 7) + ((lane >> 4) << 3);
                int c = ks*2 + ((lane >> 3) & 1);
                int csw = c ^ ((row >> 1) & 3);
                u32 a = cur + (u32)(8192 + row*64 + csw*16);
                ldsm4(bh[np], a);
                ldsm4(bl[np], a + 8192);
            }
            #pragma unroll
            for (int mt = 0; mt < 2; mt++)
                #pragma unroll
                for (int nt = 0; nt < 4; nt++){
                    u32 b0h = bh[nt >> 1][(nt & 1)*2], b1h = bh[nt >> 1][(nt & 1)*2 + 1];
                    u32 b0l = bl[nt >> 1][(nt & 1)*2], b1l = bl[nt >> 1][(nt & 1)*2 + 1];
                    mma16816(acc[mt][nt], ah[mt], b0h, b1h);
                    mma16816(acc[mt][nt], ah[mt], b0l, b1l);
                    mma16816(acc[mt][nt], al[mt], b0h, b1h);
                }
        }
        st++; if (st >= 3) st -= 3;
    }
    #undef FILL

    int g = lane >> 2, t = lane & 3;
    #pragma unroll
    for (int mt = 0; mt < 2; mt++){
        #pragma unroll
        for (int nt = 0; nt < 4; nt++){
            int col = n0 + wn*32 + nt*8 + 2*t;
            if (col >= NN) continue;
            int row = m0 + wm*32 + mt*16 + g;
            float* d = acc[mt][nt];
            *(float2*)(C + (size_t)row*NN + col)       = make_float2(d[0], d[1]);
            *(float2*)(C + (size_t)(row + 8)*NN + col) = make_float2(d[2], d[3]);
            if (write_split){
                __nv_bfloat162 hv, lv;
                hv.x = __float2bfloat16(d[0]);
                lv.x = __float2bfloat16(d[0] - __bfloat162float(hv.x));
                hv.y = __float2bfloat16(d[1]);
                lv.y = __float2bfloat16(d[1] - __bfloat162float(hv.y));
                *(__nv_bfloat162*)(Chi + (size_t)row*SW + col) = hv;
                *(__nv_bfloat162*)(Clo + (size_t)row*SW + col) = lv;
                hv.x = __float2bfloat16(d[2]);
                lv.x = __float2bfloat16(d[2] - __bfloat162float(hv.x));
                hv.y = __float2bfloat16(d[3]);
                lv.y = __float2bfloat16(d[3] - __bfloat162float(hv.y));
                *(__nv_bfloat162*)(Chi + (size_t)(row + 8)*SW + col) = hv;
                *(__nv_bfloat162*)(Clo + (size_t)(row + 8)*SW + col) = lv;
            }
        }
    }
}

// ---------------------------------------------------------------------------
// QUAD bf16 HMMA GEMM: z in {0..3} selects B operand / output; A is always
// the hg split. Same proven core, no split-write.
// ---------------------------------------------------------------------------
__global__ void __launch_bounds__(256, 3) mma_gemm_quad(
    const __nv_bfloat16* __restrict__ Ah, const __nv_bfloat16* __restrict__ Al,
    const __nv_bfloat16* __restrict__ B0h, const __nv_bfloat16* __restrict__ B0l,
    const __nv_bfloat16* __restrict__ B1h, const __nv_bfloat16* __restrict__ B1l,
    const __nv_bfloat16* __restrict__ B2h, const __nv_bfloat16* __restrict__ B2l,
    const __nv_bfloat16* __restrict__ B3h, const __nv_bfloat16* __restrict__ B3l,
    float* __restrict__ C0, float* __restrict__ C1,
    float* __restrict__ C2, float* __restrict__ C3)
{
    extern __shared__ __align__(128) char smem[];
    const u32 sb = smem_u32(smem);
    const int tid = threadIdx.x;
    const int wid = tid >> 5, lane = tid & 31;
    const int wm = wid >> 2, wn = wid & 3;
    const int m0 = blockIdx.x << 6, n0 = blockIdx.y << 7;
    const int z = blockIdx.z;

    const __nv_bfloat16* Bhi = (z == 0) ? B0h : (z == 1) ? B1h : (z == 2) ? B2h : B3h;
    const __nv_bfloat16* Blo = (z == 0) ? B0l : (z == 1) ? B1l : (z == 2) ? B2l : B3l;
    float* C = (z == 0) ? C0 : (z == 1) ? C1 : (z == 2) ? C2 : C3;

    float acc[2][4][4];
    #pragma unroll
    for (int mt = 0; mt < 2; mt++)
        #pragma unroll
        for (int nt = 0; nt < 4; nt++)
            #pragma unroll
            for (int r = 0; r < 4; r++) acc[mt][nt][r] = 0.f;

    const __nv_bfloat16* baseAh = Ah + (size_t)m0*SW;
    const __nv_bfloat16* baseAl = Al + (size_t)m0*SW;
    const __nv_bfloat16* baseBh = Bhi + (size_t)n0*SW;
    const __nv_bfloat16* baseBl = Blo + (size_t)n0*SW;

    const int fr = tid >> 2, fc = tid & 3;
    const int fr2 = fr + 64;
    const u32 fdA  = (u32)(fr*64  + (fc ^ ((fr  >> 1) & 3))*16);
    const u32 fdB2 = (u32)(fr2*64 + (fc ^ ((fr2 >> 1) & 3))*16);
    const size_t fsA  = (size_t)fr*SW  + fc*8;
    const size_t fsB2 = (size_t)fr2*SW + fc*8;

    #define FILL(kc, bufaddr) do {                                   \
        size_t ko = (size_t)(kc)*32;                                 \
        cp16((bufaddr) +     0 + fdA,  baseAh + fsA  + ko);          \
        cp16((bufaddr) +  4096 + fdA,  baseAl + fsA  + ko);          \
        cp16((bufaddr) +  8192 + fdA,  baseBh + fsA  + ko);          \
        cp16((bufaddr) +  8192 + fdB2, baseBh + fsB2 + ko);          \
        cp16((bufaddr) + 16384 + fdA,  baseBl + fsA  + ko);          \
        cp16((bufaddr) + 16384 + fdB2, baseBl + fsB2 + ko);          \
        cp_commit();                                                 \
    } while(0)

    FILL(0, sb);
    FILL(1, sb + 24576);

    int st = 0;
    #pragma unroll 1
    for (int kc = 0; kc < 16; kc++){
        u32 cur = sb + (u32)st*24576;
        if (kc + 1 < 16) cp_wait<1>();
        else             cp_wait<0>();
        __syncthreads();
        if (kc + 2 < 16){
            int ns = st + 2; if (ns >= 3) ns -= 3;
            FILL(kc + 2, sb + (u32)ns*24576);
        }

        #pragma unroll
        for (int ks = 0; ks < 2; ks++){
            u32 ah[2][4], al[2][4], bh[2][4], bl[2][4];
            #pragma unroll
            for (int mt = 0; mt < 2; mt++){
                int row = wm*32 + mt*16 + (lane & 15);
                int c = ks*2 + (lane >> 4);
                int csw = c ^ ((row >> 1) & 3);
                u32 a = cur + (u32)(row*64 + csw*16);
                ldsm4(ah[mt], a);
                ldsm4(al[mt], a + 4096);
            }
            #pragma unroll
            for (int np = 0; np < 2; np++){
                int row = wn*32 + np*16 + (lane & 7) + ((lane >> 4) << 3);
                int c = ks*2 + ((lane >> 3) & 1);
                int csw = c ^ ((row >> 1) & 3);
                u32 a = cur + (u32)(8192 + row*64 + csw*16);
                ldsm4(bh[np], a);
                ldsm4(bl[np], a + 8192);
            }
            #pragma unroll
            for (int mt = 0; mt < 2; mt++)
                #pragma unroll
                for (int nt = 0; nt < 4; nt++){
                    u32 b0h = bh[nt >> 1][(nt & 1)*2], b1h = bh[nt >> 1][(nt & 1)*2 + 1];
                    u32 b0l = bl[nt >> 1][(nt & 1)*2], b1l = bl[nt >> 1][(nt & 1)*2 + 1];
                    mma16816(acc[mt][nt], ah[mt], b0h, b1h);
                    mma16816(acc[mt][nt], ah[mt], b0l, b1l);
                    mma16816(acc[mt][nt], al[mt], b0h, b1h);
                }
        }
        st++; if (st >= 3) st -= 3;
    }
    #undef FILL

    int g = lane >> 2, t = lane & 3;
    #pragma unroll
    for (int mt = 0; mt < 2; mt++){
        #pragma unroll
        for (int nt = 0; nt < 4; nt++){
            int col = n0 + wn*32 + nt*8 + 2*t;
            if (col >= NN) continue;
            int row = m0 + wm*32 + mt*16 + g;
            float* d = acc[mt][nt];
            *(float2*)(C + (size_t)row*NN + col)       = make_float2(d[0], d[1]);
            *(float2*)(C + (size_t)(row + 8)*NN + col) = make_float2(d[2], d[3]);
        }
    }
}

// ---------------------------------------------------------------------------
// combine on COMPACT slots
// ---------------------------------------------------------------------------
__global__ void __launch_bounds__(128) combine_kernel(
    const float* __restrict__ hg,  const float* __restrict__ p1a,
    const float* __restrict__ p2a, const float* __restrict__ p1b,
    const float* __restrict__ p2b, const float* __restrict__ res,
    float* __restrict__ hout,
    const float* __restrict__ gw,  const float* __restrict__ gb,
    const float* __restrict__ bng, const float* __restrict__ bnb,
    int Cout, int Cin)
{
    __shared__ __align__(16) u64 wpk[160][32];
    int tid = threadIdx.x;
    for (int idx = tid; idx < 160*32; idx += 128){
        int c = idx >> 5, o = idx & 31;
        wpk[c][o] = pack_dup(gw[o*160 + c]);
    }
    __syncthreads();
    int b = blockIdx.z, m = blockIdx.y;
    int n = (blockIdx.x*128 + tid)*2;
    if (n >= NN) return;

    u64 acc[32];
    #pragma unroll
    for (int o = 0; o < 32; o++) acc[o] = 0ull;

    size_t pt = ((size_t)(b*32)*Cout + m)*NN + n;
    size_t cs = (size_t)Cout*NN;
    #pragma unroll 1
    for (int s5 = 0; s5 < 5; s5++){
        const float* p = (s5 == 0 ? hg : s5 == 1 ? p1a : s5 == 2 ? p2a : s5 == 3 ? p1b : p2b) + pt;
        for (int cc = 0; cc < 32; cc++){
            u64 in = *(const u64*)(p + cc*cs);
            const u64* w = &wpk[s5*32 + cc][0];
            #pragma unroll
            for (int j = 0; j < 16; j++){
                ulonglong2 wv = *(const ulonglong2*)(w + 2*j);
                fma2(acc[2*j],   wv.x, in);
                fma2(acc[2*j+1], wv.y, in);
            }
        }
    }
    const float invs = 1.0f / sqrtf(1.0f + 1e-5f);
    #pragma unroll
    for (int o = 0; o < 32; o++){
        float2 a = unpack2(acc[o]);
        float2 r = *(const float2*)(res + ((size_t)(b*32 + o)*Cin + 2*m)*NN + n);
        float sc = bng[o]*invs, bbv = bnb[o], gbv = gb[o];
        float2 out;
        out.x = (a.x + gbv + r.x)*sc + bbv;
        out.y = (a.y + gbv + r.y)*sc + bbv;
        *(float2*)(hout + ((size_t)(b*32 + o)*Cout + m)*NN + n) = out;
    }
}

// ---------------------------------------------------------------------------
// end convs (T=1): end1 8 outputs/block, end2 4 outputs/block
// ---------------------------------------------------------------------------
__global__ void __launch_bounds__(128) end1_kernel(
    const float* __restrict__ sk, const float* __restrict__ w,
    const float* __restrict__ b1, float* __restrict__ e1)
{
    __shared__ __align__(16) float ws[256*8];
    int o0 = blockIdx.y*8, b = blockIdx.z, tid = threadIdx.x;
    for (int i = tid; i < 256*8; i += 128){
        int c = i >> 3, j = i & 7;
        ws[i] = w[(o0 + j)*256 + c];
    }
    __syncthreads();
    int n = blockIdx.x*128 + tid;
    if (n >= NN) return;
    float acc[8];
    #pragma unroll
    for (int j = 0; j < 8; j++) acc[j] = b1[o0 + j];
    const float* sp = sk + (size_t)b*SCC*NN + n;
    #pragma unroll 4
    for (int c = 0; c < 256; c++){
        float v = fmaxf(sp[(size_t)c*NN], 0.f);
        float4 w0 = *(const float4*)&ws[c*8];
        float4 w1 = *(const float4*)&ws[c*8 + 4];
        acc[0] += w0.x*v; acc[1] += w0.y*v; acc[2] += w0.z*v; acc[3] += w0.w*v;
        acc[4] += w1.x*v; acc[5] += w1.y*v; acc[6] += w1.z*v; acc[7] += w1.w*v;
    }
    #pragma unroll
    for (int j = 0; j < 8; j++)
        e1[((size_t)b*512 + o0 + j)*NN + n] = fmaxf(acc[j], 0.f);
}

__global__ void __launch_bounds__(128) end2_kernel(
    const float* __restrict__ e1g, const float* __restrict__ w,
    const float* __restrict__ b2, float* __restrict__ out)
{
    __shared__ __align__(16) float ws[512*4];
    int o0 = blockIdx.y*4, b = blockIdx.z, tid = threadIdx.x;
    for (int i = tid; i < 512*4; i += 128){
        int c = i >> 2, j = i & 3;
        ws[i] = w[(o0 + j)*512 + c];
    }
    __syncthreads();
    int n = blockIdx.x*128 + tid;
    if (n >= NN) return;
    float acc[4];
    #pragma unroll
    for (int j = 0; j < 4; j++) acc[j] = b2[o0 + j];
    const float* p = e1g + (size_t)b*512*NN + n;
    #pragma unroll 4
    for (int c = 0; c < 512; c++){
        float v = p[(size_t)c*NN];
        float4 w4 = *(const float4*)&ws[c*4];
        acc[0] += w4.x*v; acc[1] += w4.y*v; acc[2] += w4.z*v; acc[3] += w4.w*v;
    }
    #pragma unroll
    for (int j = 0; j < 4; j++)
        out[((size_t)b*12 + o0 + j)*NN + n] = acc[j];
}

// ---------------------------------------------------------------------------
extern "C" void kernel_launch(void* const* d_in, const int* in_sizes, int n_in,
                              void* d_out, int out_size)
{
    const float* x       = (const float*)d_in[0];
    const float* A0      = (const float*)d_in[1];
    const float* start_w = (const float*)d_in[2];
    const float* start_b = (const float*)d_in[3];
    const float* filt_w  = (const float*)d_in[4];
    const float* filt_b  = (const float*)d_in[5];
    const float* gate_w  = (const float*)d_in[6];
    const float* gate_b  = (const float*)d_in[7];
    const float* skip_w  = (const float*)d_in[8];
    const float* skip_b  = (const float*)d_in[9];
    const float* gcn_w   = (const float*)d_in[10];
    const float* gcn_b   = (const float*)d_in[11];
    const float* bn_g    = (const float*)d_in[12];
    const float* bn_b    = (const float*)d_in[13];
    const float* nv1     = (const float*)d_in[14];
    const float* nv2     = (const float*)d_in[15];
    const float* e1w     = (const float*)d_in[16];
    const float* e1b     = (const float*)d_in[17];
    const float* e2w     = (const float*)d_in[18];
    const float* e2b     = (const float*)d_in[19];
    float* out = (float*)d_out;

    float *h0, *h1, *hg, *p1a, *p2a, *p1b, *p2b, *skip, *e1;
    __nv_bfloat16 *hgh, *hgl;
    __nv_bfloat16 *bt0h, *bt0l, *bt1h, *bt1l;
    __nv_bfloat16 *a0rh, *a0rl, *a1rh, *a1rl;
    __nv_bfloat16 *bt0sh, *bt0sl, *bt1sh, *bt1sl;
    cudaGetSymbolAddress((void**)&h0,  g_h0);
    cudaGetSymbolAddress((void**)&h1,  g_h1);
    cudaGetSymbolAddress((void**)&hg,  g_hg);
    cudaGetSymbolAddress((void**)&p1a, g_p1a);
    cudaGetSymbolAddress((void**)&p2a, g_p2a);
    cudaGetSymbolAddress((void**)&p1b, g_p1b);
    cudaGetSymbolAddress((void**)&p2b, g_p2b);
    cudaGetSymbolAddress((void**)&skip, g_skip);
    cudaGetSymbolAddress((void**)&e1,  g_e1);
    cudaGetSymbolAddress((void**)&hgh,  g_hg_hi);
    cudaGetSymbolAddress((void**)&hgl,  g_hg_lo);
    cudaGetSymbolAddress((void**)&bt0h, g_bt0_hi);
    cudaGetSymbolAddress((void**)&bt0l, g_bt0_lo);
    cudaGetSymbolAddress((void**)&bt1h, g_bt1_hi);
    cudaGetSymbolAddress((void**)&bt1l, g_bt1_lo);
    cudaGetSymbolAddress((void**)&a0rh, g_a0r_hi);
    cudaGetSymbolAddress((void**)&a0rl, g_a0r_lo);
    cudaGetSymbolAddress((void**)&a1rh, g_a1r_hi);
    cudaGetSymbolAddress((void**)&a1rl, g_a1r_lo);
    cudaGetSymbolAddress((void**)&bt0sh, g_bt0s_hi);
    cudaGetSymbolAddress((void**)&bt0sl, g_bt0s_lo);
    cudaGetSymbolAddress((void**)&bt1sh, g_bt1s_hi);
    cudaGetSymbolAddress((void**)&bt1sl, g_bt1s_lo);

    const int MMA_SMEM = 3*24576;
    cudaFuncSetAttribute(mma_gemm_dual, cudaFuncAttributeMaxDynamicSharedMemorySize, MMA_SMEM);
    cudaFuncSetAttribute(mma_gemm_quad, cudaFuncAttributeMaxDynamicSharedMemorySize, MMA_SMEM);

    start_conv_kernel<<<dim3(TT0/32, (NN + 31)/32, BB), 256>>>(x, start_w, start_b, h0);

    int Cin = TT0;
    float* hcur = h0;
    float* hnext = h1;
    for (int i = 0; i < 8; i++){
        int Cout = Cin >> 1;

        gated_conv_kernel<<<dim3(2, Cout, BB), 256>>>(
            hcur, hg, hgh, hgl,
            filt_w + (size_t)i*32*32*2, filt_b + (size_t)i*32,
            gate_w + (size_t)i*32*32*2, gate_b + (size_t)i*32,
            Cin, Cout);

        if (i == 0){
            prep_kernel<<<NN, 512>>>(A0, nv1, nv2, bt0h, bt0l, bt1h, bt1l,
                                     a0rh, a0rl, a1rh, a1rl);
            // square the adjacencies: bt_s[n][k] = (Adj^2)[k][n]
            mma_gemm_dual<<<dim3(8, 4, 2), 256, MMA_SMEM>>>(
                bt0h, bt0l, bt1h, bt1l,
                a0rh, a0rl, a1rh, a1rl,
                p2a, p2b,                    // fp32 scratch, overwritten later
                bt0sh, bt0sl, bt1sh, bt1sl, 1);
        }

        if (i < 7){
            int M = BB*CH*Cout;
            dim3 gg(M >> 6, 4, 4);
            mma_gemm_quad<<<gg, 256, MMA_SMEM>>>(
                hgh, hgl,
                bt0h, bt0l, bt1h, bt1l,
                bt0sh, bt0sl, bt1sh, bt1sl,
                p1a, p1b, p2a, p2b);
        }

        skip_kernel<<<dim3(4, SCC/8, BB), 128>>>(
            hg, skip_w + (size_t)i*SCC*32, skip_b + (size_t)i*SCC,
            skip, Cout, (i == 0) ? 1 : 0);

        if (i < 7){
            combine_kernel<<<dim3(2, Cout, BB), 128>>>(
                hg, p1a, p2a, p1b, p2b, hcur, hnext,
                gcn_w + (size_t)i*32*160, gcn_b + (size_t)i*32,
                bn_g + (size_t)i*32, bn_b + (size_t)i*32,
                Cout, Cin);

            float* tmp = hcur; hcur = hnext; hnext = tmp;
        }
        Cin = Cout;
    }

    end1_kernel<<<dim3(4, 512/8, BB), 128>>>(skip, e1w, e1b, e1);
    end2_kernel<<<dim3(4, 12/4, BB), 128>>>(e1, e2w, e2b, out);
}